// round 10
// baseline (speedup 1.0000x reference)
#include <cuda_runtime.h>
#include <math.h>
#include <stdint.h>

#define NB 16
#define NC 512
#define NHW 1024
#define NHEADS 8
#define HD 64
#define NG 32
#define OC3 1536
#define GN_EPS 1e-5f

typedef unsigned short ushort_t;

// Scratch (static device globals — allocation-free per harness rules)
__device__ ushort_t g_wqhi[(size_t)OC3 * NC];
__device__ ushort_t g_wqlo[(size_t)OC3 * NC];
__device__ ushort_t g_wphi[(size_t)NC * NC];
__device__ ushort_t g_wplo[(size_t)NC * NC];
__device__ ushort_t g_xnhi[(size_t)NB * NC * NHW];
__device__ ushort_t g_xnlo[(size_t)NB * NC * NHW];
__device__ ushort_t g_qkvhi[(size_t)NB * OC3 * NHW];
__device__ ushort_t g_qkvlo[(size_t)NB * OC3 * NHW];
__device__ ushort_t g_atthi[(size_t)NB * NC * NHW];
__device__ ushort_t g_attlo[(size_t)NB * NC * NHW];

// ============================ helpers ======================================
__device__ __forceinline__ uint32_t smem_u32(const void* p) {
  uint32_t a;
  asm("{ .reg .u64 t; cvta.to.shared.u64 t, %1; cvt.u32.u64 %0, t; }"
      : "=r"(a) : "l"(p));
  return a;
}
__device__ __forceinline__ uint32_t packbf2(float lo16, float hi16) {
  uint32_t r;
  asm("cvt.rn.bf16x2.f32 %0, %1, %2;" : "=r"(r) : "f"(hi16), "f"(lo16));
  return r;
}
__device__ __forceinline__ float bflo_f(uint32_t u) {
  return __uint_as_float(u << 16);
}
__device__ __forceinline__ float bfhi_f(uint32_t u) {
  return __uint_as_float(u & 0xffff0000u);
}
__device__ __forceinline__ void ldsm_x4(uint32_t* r, uint32_t addr) {
  asm volatile("ldmatrix.sync.aligned.m8n8.x4.shared.b16 {%0,%1,%2,%3}, [%4];"
               : "=r"(r[0]), "=r"(r[1]), "=r"(r[2]), "=r"(r[3]) : "r"(addr));
}
__device__ __forceinline__ void ldsm_x4_t(uint32_t* r, uint32_t addr) {
  asm volatile(
      "ldmatrix.sync.aligned.m8n8.x4.trans.shared.b16 {%0,%1,%2,%3}, [%4];"
      : "=r"(r[0]), "=r"(r[1]), "=r"(r[2]), "=r"(r[3]) : "r"(addr));
}
__device__ __forceinline__ void mma16816(float* d, const uint32_t* a,
                                         const uint32_t* b) {
  asm volatile(
      "mma.sync.aligned.m16n8k16.row.col.f32.bf16.bf16.f32 "
      "{%0,%1,%2,%3}, {%4,%5,%6,%7}, {%8,%9}, {%0,%1,%2,%3};"
      : "+f"(d[0]), "+f"(d[1]), "+f"(d[2]), "+f"(d[3])
      : "r"(a[0]), "r"(a[1]), "r"(a[2]), "r"(a[3]), "r"(b[0]), "r"(b[1]));
}

// ---------------------------------------------------------------------------
// Weight prep: fp32 -> hi/lo bf16 planes (once per launch)
// ---------------------------------------------------------------------------
__global__ void __launch_bounds__(256) prep_w_kernel(
    const float* __restrict__ qkv_w, const float* __restrict__ proj_w) {
  const int idx = blockIdx.x * 256 + threadIdx.x;
  const int nq = OC3 * NC / 4;
  const float* src;
  ushort_t *dh, *dl;
  int off;
  if (idx < nq) {
    src = qkv_w; dh = g_wqhi; dl = g_wqlo; off = idx * 4;
  } else {
    src = proj_w; dh = g_wphi; dl = g_wplo; off = (idx - nq) * 4;
  }
  float4 v = *(const float4*)(src + off);
  uint32_t h01 = packbf2(v.x, v.y), h23 = packbf2(v.z, v.w);
  uint32_t l01 = packbf2(v.x - bflo_f(h01), v.y - bfhi_f(h01));
  uint32_t l23 = packbf2(v.z - bflo_f(h23), v.w - bfhi_f(h23));
  *(uint2*)(dh + off) = make_uint2(h01, h23);
  *(uint2*)(dl + off) = make_uint2(l01, l23);
}

// ---------------------------------------------------------------------------
// GroupNorm -> hi/lo bf16 planes
// ---------------------------------------------------------------------------
__global__ void __launch_bounds__(256) gn_kernel(
    const float* __restrict__ x, const float* __restrict__ gamma,
    const float* __restrict__ beta) {
  const int bg = blockIdx.x;
  const int g = bg & (NG - 1);
  const size_t base = (size_t)bg * (NC / NG) * NHW;
  const float* px = x + base;
  ushort_t* poh = g_xnhi + base;
  ushort_t* pol = g_xnlo + base;
  const int tid = threadIdx.x;

  float s = 0.f, q = 0.f;
#pragma unroll
  for (int k = 0; k < 16; k++) {
    float4 v = *(const float4*)(px + (size_t)(tid + k * 256) * 4);
    s += v.x + v.y + v.z + v.w;
    q += v.x * v.x + v.y * v.y + v.z * v.z + v.w * v.w;
  }
#pragma unroll
  for (int off = 16; off; off >>= 1) {
    s += __shfl_xor_sync(0xffffffffu, s, off);
    q += __shfl_xor_sync(0xffffffffu, q, off);
  }
  __shared__ float ss[8], sq[8];
  __shared__ float s_mean, s_inv;
  const int w = tid >> 5;
  if ((tid & 31) == 0) { ss[w] = s; sq[w] = q; }
  __syncthreads();
  if (tid == 0) {
    float ts = 0.f, tq = 0.f;
#pragma unroll
    for (int i = 0; i < 8; i++) { ts += ss[i]; tq += sq[i]; }
    float mean = ts * (1.f / 16384.f);
    float var = tq * (1.f / 16384.f) - mean * mean;
    s_mean = mean;
    s_inv = rsqrtf(var + GN_EPS);
  }
  __syncthreads();
  const float mean = s_mean, inv = s_inv;
#pragma unroll
  for (int k = 0; k < 16; k++) {
    size_t off = (size_t)(tid + k * 256) * 4;
    int c = g * 16 + (int)(off >> 10);
    float ga = gamma[c], be = beta[c];
    float4 v = *(const float4*)(px + off);
    v.x = (v.x - mean) * inv * ga + be;
    v.y = (v.y - mean) * inv * ga + be;
    v.z = (v.z - mean) * inv * ga + be;
    v.w = (v.w - mean) * inv * ga + be;
    uint32_t h01 = packbf2(v.x, v.y), h23 = packbf2(v.z, v.w);
    uint32_t l01 = packbf2(v.x - bflo_f(h01), v.y - bfhi_f(h01));
    uint32_t l23 = packbf2(v.z - bflo_f(h23), v.w - bfhi_f(h23));
    *(uint2*)(poh + off) = make_uint2(h01, h23);
    *(uint2*)(pol + off) = make_uint2(l01, l23);
  }
}

// ---------------------------------------------------------------------------
// bf16 GEMM (3-term split), double-buffered smem + reg prefetch, one sync
// per chunk, term-major MMA ordering (16-deep accumulator reuse distance).
// Tile 128(o) x 128(t), K-chunk 32; 8 warps = 4m x 2n; warp 32x64.
// ---------------------------------------------------------------------------
#define SAH 40
#define SBH 136
#define A_ELE (2 * 128 * SAH)           // both planes
#define B_ELE (2 * 32 * SBH)
#define BUF_ELE (A_ELE + B_ELE)
#define GEMM_SMEM (2 * BUF_ELE * (int)sizeof(ushort_t))

template <int OC, bool EMIT>
__global__ void __launch_bounds__(256) gemm_bf16_kernel(
    const ushort_t* __restrict__ Ahi, const ushort_t* __restrict__ Alo,
    const float* __restrict__ bias, const ushort_t* __restrict__ Bhi,
    const ushort_t* __restrict__ Blo, const float* __restrict__ R,
    float* __restrict__ Yf, ushort_t* __restrict__ Yhi,
    ushort_t* __restrict__ Ylo) {
  extern __shared__ __align__(16) ushort_t smem[];

  const int tid = threadIdx.x, lane = tid & 31, wid = tid >> 5;
  const int wm = wid >> 1, wn = wid & 1;
  const int bz = blockIdx.z;
  const int o0 = blockIdx.y * 128;
  const int t0 = blockIdx.x * 128;
  const size_t bb = (size_t)bz * NC * NHW;

  const int a_r = lane & 15, a_c = (lane >> 4) << 3;
  const int b_g = lane >> 3;
  const int b_row = ((b_g & 1) << 3) + (lane & 7);
  const int b_col = (b_g >> 1) << 3;

  float acc[2][8][4] = {};
  uint4 pa[4], pb[4];

#define LOAD_REGS(kc)                                                        \
  {                                                                          \
    _Pragma("unroll") for (int i = 0; i < 4; i++) {                          \
      const int idx = i * 256 + tid;                                         \
      const int pl = idx >> 9, r = (idx >> 2) & 127, cc = idx & 3;           \
      pa[i] = *(const uint4*)((pl ? Alo : Ahi) + (size_t)(o0 + r) * NC +     \
                              (kc) + cc * 8);                                \
    }                                                                        \
    _Pragma("unroll") for (int i = 0; i < 4; i++) {                          \
      const int idx = i * 256 + tid;                                         \
      const int pl = idx >> 9, r = (idx >> 4) & 31, cc = idx & 15;           \
      pb[i] = *(const uint4*)((pl ? Blo : Bhi) + bb +                        \
                              (size_t)((kc) + r) * NHW + t0 + cc * 8);       \
    }                                                                        \
  }
#define STORE_SMEM(buf)                                                      \
  {                                                                          \
    ushort_t* Asm = smem + (buf)*BUF_ELE;                                    \
    ushort_t* Bsm = Asm + A_ELE;                                             \
    _Pragma("unroll") for (int i = 0; i < 4; i++) {                          \
      const int idx = i * 256 + tid;                                         \
      const int pl = idx >> 9, r = (idx >> 2) & 127, cc = idx & 3;           \
      *(uint4*)&Asm[pl * 128 * SAH + r * SAH + cc * 8] = pa[i];              \
    }                                                                        \
    _Pragma("unroll") for (int i = 0; i < 4; i++) {                          \
      const int idx = i * 256 + tid;                                         \
      const int pl = idx >> 9, r = (idx >> 4) & 31, cc = idx & 15;           \
      *(uint4*)&Bsm[pl * 32 * SBH + r * SBH + cc * 8] = pb[i];               \
    }                                                                        \
  }

  LOAD_REGS(0);
  STORE_SMEM(0);
  __syncthreads();

#pragma unroll 1
  for (int chunk = 0; chunk < NC / 32; chunk++) {
    const int cur = chunk & 1;
    if (chunk < NC / 32 - 1) LOAD_REGS((chunk + 1) * 32);
    const ushort_t* Asm = smem + cur * BUF_ELE;
    const ushort_t* Bsm = Asm + A_ELE;
#pragma unroll
    for (int ks = 0; ks < 2; ks++) {
      const int kb = ks * 16;
      uint32_t ah[2][4], al[2][4], kbh[4][4], kbl[4][4];
#pragma unroll
      for (int mf = 0; mf < 2; mf++) {
        const int ao = (wm * 32 + mf * 16 + a_r) * SAH + kb + a_c;
        ldsm_x4(ah[mf], smem_u32(&Asm[ao]));
        ldsm_x4(al[mf], smem_u32(&Asm[128 * SAH + ao]));
      }
#pragma unroll
      for (int nb = 0; nb < 4; nb++) {
        const int bo = (kb + b_row) * SBH + wn * 64 + nb * 16 + b_col;
        ldsm_x4_t(kbh[nb], smem_u32(&Bsm[bo]));
        ldsm_x4_t(kbl[nb], smem_u32(&Bsm[32 * SBH + bo]));
      }
      // term-major: 16 distinct accumulators between same-acc reuse
#pragma unroll
      for (int nb = 0; nb < 4; nb++)
#pragma unroll
        for (int mf = 0; mf < 2; mf++) {
          mma16816(acc[mf][2 * nb], ah[mf], &kbh[nb][0]);
          mma16816(acc[mf][2 * nb + 1], ah[mf], &kbh[nb][2]);
        }
#pragma unroll
      for (int nb = 0; nb < 4; nb++)
#pragma unroll
        for (int mf = 0; mf < 2; mf++) {
          mma16816(acc[mf][2 * nb], ah[mf], &kbl[nb][0]);
          mma16816(acc[mf][2 * nb + 1], ah[mf], &kbl[nb][2]);
        }
#pragma unroll
      for (int nb = 0; nb < 4; nb++)
#pragma unroll
        for (int mf = 0; mf < 2; mf++) {
          mma16816(acc[mf][2 * nb], al[mf], &kbh[nb][0]);
          mma16816(acc[mf][2 * nb + 1], al[mf], &kbh[nb][2]);
        }
    }
    if (chunk < NC / 32 - 1) {
      STORE_SMEM(cur ^ 1);
    }
    __syncthreads();
  }

#pragma unroll
  for (int mf = 0; mf < 2; mf++)
#pragma unroll
    for (int nf = 0; nf < 8; nf++) {
      const int o = o0 + wm * 32 + mf * 16 + (lane >> 2);
      const int t = t0 + wn * 64 + nf * 8 + ((lane & 3) << 1);
      const size_t off0 = ((size_t)bz * OC + o) * NHW + t;
      const size_t off1 = off0 + (size_t)8 * NHW;
      const float bi0 = bias[o], bi1 = bias[o + 8];
      float y0 = acc[mf][nf][0] + bi0, y1 = acc[mf][nf][1] + bi0;
      float y2 = acc[mf][nf][2] + bi1, y3 = acc[mf][nf][3] + bi1;
      if (EMIT) {
        uint32_t h01 = packbf2(y0, y1), h23 = packbf2(y2, y3);
        uint32_t l01 = packbf2(y0 - bflo_f(h01), y1 - bfhi_f(h01));
        uint32_t l23 = packbf2(y2 - bflo_f(h23), y3 - bfhi_f(h23));
        *(uint32_t*)(Yhi + off0) = h01;
        *(uint32_t*)(Yhi + off1) = h23;
        *(uint32_t*)(Ylo + off0) = l01;
        *(uint32_t*)(Ylo + off1) = l23;
      } else {
        float2 r0 = *(const float2*)(R + off0);
        float2 r1 = *(const float2*)(R + off1);
        *(float2*)(Yf + off0) = make_float2(y0 + r0.x, y1 + r0.y);
        *(float2*)(Yf + off1) = make_float2(y2 + r1.x, y3 + r1.y);
      }
    }
#undef LOAD_REGS
#undef STORE_SMEM
}

// ---------------------------------------------------------------------------
// Flash attention, m32 warp tiles, term-major MMA ordering.
// CTA: (b,h, t-tile 256); keys in 128-tiles processed in 64-wide halves.
// ---------------------------------------------------------------------------
#define SQH 264
#define AQH 136
#define AVH 72

__global__ void __launch_bounds__(256) attn_mma_kernel(
    const ushort_t* __restrict__ qkvhi, const ushort_t* __restrict__ qkvlo,
    ushort_t* __restrict__ outhi, ushort_t* __restrict__ outlo) {
  extern __shared__ __align__(16) ushort_t smem[];
  ushort_t* Qh = smem;
  ushort_t* Ql = Qh + 64 * SQH;
  ushort_t* Kh = Ql + 64 * SQH;
  ushort_t* Kl = Kh + 64 * AQH;
  ushort_t* Vh = Kl + 64 * AQH;
  ushort_t* Vl = Vh + 128 * AVH;

  const int tid = threadIdx.x, lane = tid & 31, warp = tid >> 5;
  const int bh_ = blockIdx.y;
  const int b = bh_ >> 3, h = bh_ & 7;
  const int t0 = blockIdx.x * 256;

  const ushort_t* qhp = qkvhi + ((size_t)b * OC3 + h * HD) * NHW;
  const ushort_t* qlp = qkvlo + ((size_t)b * OC3 + h * HD) * NHW;
  const ushort_t* khp = qhp + (size_t)NC * NHW;
  const ushort_t* klp = qlp + (size_t)NC * NHW;
  const ushort_t* vhp = qhp + (size_t)2 * NC * NHW;
  const ushort_t* vlp = qlp + (size_t)2 * NC * NHW;

#pragma unroll
  for (int i = 0; i < 16; i++) {
    const int idx = i * 256 + tid;
    const int pl = idx >> 11, r = (idx >> 5) & 63, c = idx & 31;
    ushort_t* dst = (pl ? Ql : Qh) + r * SQH + c * 8;
    const ushort_t* src = (pl ? qlp : qhp) + (size_t)r * NHW + t0 + c * 8;
    *(uint4*)dst = *(const uint4*)src;
  }
  __syncthreads();

  const int a_kr = ((lane >> 4) << 3) + (lane & 7);
  const int a_mc = ((lane >> 3) & 1) << 3;
  const int b_g = lane >> 3;
  const int b_row = ((b_g & 1) << 3) + (lane & 7);
  const int b_col = (b_g >> 1) << 3;

  uint32_t aq[2][4][4];
#pragma unroll
  for (int mf = 0; mf < 2; mf++)
#pragma unroll
    for (int k4 = 0; k4 < 4; k4++) {
      const int ao = (k4 * 16 + a_kr) * SQH + warp * 32 + mf * 16 + a_mc;
      ldsm_x4_t(aq[mf][k4], smem_u32(&Qh[ao]));
    }

  float o8[2][8][4] = {};
  float mM[2][2], lL[2][2];
#pragma unroll
  for (int mf = 0; mf < 2; mf++) {
    mM[mf][0] = -1e30f; mM[mf][1] = -1e30f;
    lL[mf][0] = 0.f; lL[mf][1] = 0.f;
  }

#pragma unroll 1
  for (int s0 = 0; s0 < NHW; s0 += 128) {
#pragma unroll
    for (int i = 0; i < 8; i++) {
      const int idx = i * 256 + tid;
      const int pl = idx >> 10, r = (idx >> 4) & 63, c = idx & 15;
      ushort_t* dst = (pl ? Kl : Kh) + r * AQH + c * 8;
      const ushort_t* src = (pl ? klp : khp) + (size_t)r * NHW + s0 + c * 8;
      *(uint4*)dst = *(const uint4*)src;
    }
#pragma unroll
    for (int i = 0; i < 4; i++) {
      const int idx = i * 256 + tid;
      const int pl = idx >> 9, u = idx & 511;
      const int dp = u & 31, sc = u >> 5;
      const ushort_t* src = pl ? vlp : vhp;
      ushort_t* dst = pl ? Vl : Vh;
      uint4 r0 = *(const uint4*)(src + (size_t)(2 * dp) * NHW + s0 + sc * 8);
      uint4 r1 =
          *(const uint4*)(src + (size_t)(2 * dp + 1) * NHW + s0 + sc * 8);
      uint32_t q0[4] = {r0.x, r0.y, r0.z, r0.w};
      uint32_t q1[4] = {r1.x, r1.y, r1.z, r1.w};
#pragma unroll
      for (int j2 = 0; j2 < 4; j2++) {
        uint32_t a = q0[j2], bq = q1[j2];
        uint32_t w0 = (a & 0xffffu) | (bq << 16);
        uint32_t w1 = (a >> 16) | (bq & 0xffff0000u);
        const int s = sc * 8 + 2 * j2;
        *(uint32_t*)&dst[s * AVH + 2 * dp] = w0;
        *(uint32_t*)&dst[(s + 1) * AVH + 2 * dp] = w1;
      }
    }
    __syncthreads();

#pragma unroll
    for (int hf = 0; hf < 2; hf++) {
      uint32_t aql[2][4][4];
#pragma unroll
      for (int mf = 0; mf < 2; mf++)
#pragma unroll
        for (int k4 = 0; k4 < 4; k4++) {
          const int ao = (k4 * 16 + a_kr) * SQH + warp * 32 + mf * 16 + a_mc;
          ldsm_x4_t(aql[mf][k4], smem_u32(&Ql[ao]));
        }

      // ---- S = Q^T K, term-major per k4 ----
      float sacc[2][8][4] = {};
#pragma unroll
      for (int k4 = 0; k4 < 4; k4++) {
        uint32_t kbh[4][4], kbl[4][4];
#pragma unroll
        for (int nb = 0; nb < 4; nb++) {
          const int bo = (k4 * 16 + b_row) * AQH + hf * 64 + nb * 16 + b_col;
          ldsm_x4_t(kbh[nb], smem_u32(&Kh[bo]));
          ldsm_x4_t(kbl[nb], smem_u32(&Kl[bo]));
        }
#pragma unroll
        for (int nb = 0; nb < 4; nb++)
#pragma unroll
          for (int mf = 0; mf < 2; mf++) {
            mma16816(sacc[mf][2 * nb], aq[mf][k4], &kbh[nb][0]);
            mma16816(sacc[mf][2 * nb + 1], aq[mf][k4], &kbh[nb][2]);
          }
#pragma unroll
        for (int nb = 0; nb < 4; nb++)
#pragma unroll
          for (int mf = 0; mf < 2; mf++) {
            mma16816(sacc[mf][2 * nb], aq[mf][k4], &kbl[nb][0]);
            mma16816(sacc[mf][2 * nb + 1], aq[mf][k4], &kbl[nb][2]);
          }
#pragma unroll
        for (int nb = 0; nb < 4; nb++)
#pragma unroll
          for (int mf = 0; mf < 2; mf++) {
            mma16816(sacc[mf][2 * nb], aql[mf][k4], &kbh[nb][0]);
            mma16816(sacc[mf][2 * nb + 1], aql[mf][k4], &kbh[nb][2]);
          }
      }

      // ---- online softmax + pack P ----
      uint32_t Ph[2][4][4], Pw[2][4][4];
#pragma unroll
      for (int mf = 0; mf < 2; mf++) {
        float mt0 = -1e30f, mt1 = -1e30f;
#pragma unroll
        for (int f = 0; f < 8; f++) {
          sacc[mf][f][0] *= 0.125f; sacc[mf][f][1] *= 0.125f;
          sacc[mf][f][2] *= 0.125f; sacc[mf][f][3] *= 0.125f;
          mt0 = fmaxf(mt0, fmaxf(sacc[mf][f][0], sacc[mf][f][1]));
          mt1 = fmaxf(mt1, fmaxf(sacc[mf][f][2], sacc[mf][f][3]));
        }
        mt0 = fmaxf(mt0, __shfl_xor_sync(0xffffffffu, mt0, 1));
        mt0 = fmaxf(mt0, __shfl_xor_sync(0xffffffffu, mt0, 2));
        mt1 = fmaxf(mt1, __shfl_xor_sync(0xffffffffu, mt1, 1));
        mt1 = fmaxf(mt1, __shfl_xor_sync(0xffffffffu, mt1, 2));
        const float mn0 = fmaxf(mM[mf][0], mt0);
        const float mn1 = fmaxf(mM[mf][1], mt1);
        const float fac0 = __expf(mM[mf][0] - mn0);
        const float fac1 = __expf(mM[mf][1] - mn1);
        mM[mf][0] = mn0; mM[mf][1] = mn1;
        float rs0 = 0.f, rs1 = 0.f;
#pragma unroll
        for (int f = 0; f < 8; f++) {
          sacc[mf][f][0] = __expf(sacc[mf][f][0] - mn0);
          sacc[mf][f][1] = __expf(sacc[mf][f][1] - mn0);
          sacc[mf][f][2] = __expf(sacc[mf][f][2] - mn1);
          sacc[mf][f][3] = __expf(sacc[mf][f][3] - mn1);
          rs0 += sacc[mf][f][0] + sacc[mf][f][1];
          rs1 += sacc[mf][f][2] + sacc[mf][f][3];
        }
        rs0 += __shfl_xor_sync(0xffffffffu, rs0, 1);
        rs0 += __shfl_xor_sync(0xffffffffu, rs0, 2);
        rs1 += __shfl_xor_sync(0xffffffffu, rs1, 1);
        rs1 += __shfl_xor_sync(0xffffffffu, rs1, 2);
        lL[mf][0] = lL[mf][0] * fac0 + rs0;
        lL[mf][1] = lL[mf][1] * fac1 + rs1;
#pragma unroll
        for (int f = 0; f < 8; f++) {
          o8[mf][f][0] *= fac0; o8[mf][f][1] *= fac0;
          o8[mf][f][2] *= fac1; o8[mf][f][3] *= fac1;
        }
#pragma unroll
        for (int f = 0; f < 8; f++) {
          const int k8 = f >> 1, sl = (f & 1) << 1;
          uint32_t h01 = packbf2(sacc[mf][f][0], sacc[mf][f][1]);
          uint32_t h23 = packbf2(sacc[mf][f][2], sacc[mf][f][3]);
          Ph[mf][k8][sl] = h01;
          Ph[mf][k8][sl + 1] = h23;
          Pw[mf][k8][sl] = packbf2(sacc[mf][f][0] - bflo_f(h01),
                                   sacc[mf][f][1] - bfhi_f(h01));
          Pw[mf][k8][sl + 1] = packbf2(sacc[mf][f][2] - bflo_f(h23),
                                       sacc[mf][f][3] - bfhi_f(h23));
        }
      }

      // ---- O += P V, term-major per k8 ----
#pragma unroll
      for (int k8 = 0; k8 < 4; k8++) {
        uint32_t vh[4][4], vl[4][4];
#pragma unroll
        for (int nb = 0; nb < 4; nb++) {
          const int vo = (hf * 64 + k8 * 16 + b_row) * AVH + nb * 16 + b_col;
          ldsm_x4_t(vh[nb], smem_u32(&Vh[vo]));
          ldsm_x4_t(vl[nb], smem_u32(&Vl[vo]));
        }
#pragma unroll
        for (int nb = 0; nb < 4; nb++)
#pragma unroll
          for (int mf = 0; mf < 2; mf++) {
            mma16816(o8[mf][2 * nb], Ph[mf][k8], &vh[nb][0]);
            mma16816(o8[mf][2 * nb + 1], Ph[mf][k8], &vh[nb][2]);
          }
#pragma unroll
        for (int nb = 0; nb < 4; nb++)
#pragma unroll
          for (int mf = 0; mf < 2; mf++) {
            mma16816(o8[mf][2 * nb], Ph[mf][k8], &vl[nb][0]);
            mma16816(o8[mf][2 * nb + 1], Ph[mf][k8], &vl[nb][2]);
          }
#pragma unroll
        for (int nb = 0; nb < 4; nb++)
#pragma unroll
          for (int mf = 0; mf < 2; mf++) {
            mma16816(o8[mf][2 * nb], Pw[mf][k8], &vh[nb][0]);
            mma16816(o8[mf][2 * nb + 1], Pw[mf][k8], &vh[nb][2]);
          }
      }
    }
    __syncthreads();
  }

  // ---- epilogue ----
  float* Ost = (float*)Qh;
  const float i00 = 1.f / lL[0][0], i01 = 1.f / lL[0][1];
  const float i10 = 1.f / lL[1][0], i11 = 1.f / lL[1][1];
#pragma unroll
  for (int mf = 0; mf < 2; mf++) {
    const float iv0 = mf ? i10 : i00, iv1 = mf ? i11 : i01;
    const int t = warp * 32 + mf * 16 + (lane >> 2);
#pragma unroll
    for (int f = 0; f < 8; f++) {
      const int d = f * 8 + ((lane & 3) << 1);
      Ost[d * 260 + t] = o8[mf][f][0] * iv0;
      Ost[(d + 1) * 260 + t] = o8[mf][f][1] * iv0;
      Ost[d * 260 + t + 8] = o8[mf][f][2] * iv1;
      Ost[(d + 1) * 260 + t + 8] = o8[mf][f][3] * iv1;
    }
  }
  __syncthreads();
#pragma unroll
  for (int i = 0; i < 8; i++) {
    const int idx = i * 256 + tid;
    const int r = idx >> 5, c = idx & 31;
    const float* src = &Ost[r * 260 + c * 8];
    uint32_t hu[4], lu[4];
#pragma unroll
    for (int j = 0; j < 4; j++) {
      float v0 = src[2 * j], v1 = src[2 * j + 1];
      hu[j] = packbf2(v0, v1);
      lu[j] = packbf2(v0 - bflo_f(hu[j]), v1 - bfhi_f(hu[j]));
    }
    const size_t off = ((size_t)b * NC + h * HD + r) * NHW + t0 + c * 8;
    *(uint4*)(outhi + off) = make_uint4(hu[0], hu[1], hu[2], hu[3]);
    *(uint4*)(outlo + off) = make_uint4(lu[0], lu[1], lu[2], lu[3]);
  }
}

// ---------------------------------------------------------------------------
extern "C" void kernel_launch(void* const* d_in, const int* in_sizes, int n_in,
                              void* d_out, int out_size) {
  const float* x = (const float*)d_in[0];
  const float* gn_gamma = (const float*)d_in[1];
  const float* gn_beta = (const float*)d_in[2];
  const float* qkv_w = (const float*)d_in[3];
  const float* qkv_b = (const float*)d_in[4];
  const float* proj_w = (const float*)d_in[5];
  const float* proj_b = (const float*)d_in[6];
  float* out = (float*)d_out;

  ushort_t *wqh, *wql, *wph, *wpl, *xnh, *xnl, *qh, *qlo, *ath, *atl;
  cudaGetSymbolAddress((void**)&wqh, g_wqhi);
  cudaGetSymbolAddress((void**)&wql, g_wqlo);
  cudaGetSymbolAddress((void**)&wph, g_wphi);
  cudaGetSymbolAddress((void**)&wpl, g_wplo);
  cudaGetSymbolAddress((void**)&xnh, g_xnhi);
  cudaGetSymbolAddress((void**)&xnl, g_xnlo);
  cudaGetSymbolAddress((void**)&qh, g_qkvhi);
  cudaGetSymbolAddress((void**)&qlo, g_qkvlo);
  cudaGetSymbolAddress((void**)&ath, g_atthi);
  cudaGetSymbolAddress((void**)&atl, g_attlo);

  const int ATT_SMEM =
      (2 * 64 * SQH + 2 * 64 * AQH + 2 * 128 * AVH) * (int)sizeof(ushort_t);
  cudaFuncSetAttribute(attn_mma_kernel,
                       cudaFuncAttributeMaxDynamicSharedMemorySize, ATT_SMEM);
  cudaFuncSetAttribute(gemm_bf16_kernel<OC3, true>,
                       cudaFuncAttributeMaxDynamicSharedMemorySize, GEMM_SMEM);
  cudaFuncSetAttribute(gemm_bf16_kernel<NC, false>,
                       cudaFuncAttributeMaxDynamicSharedMemorySize, GEMM_SMEM);

  gn_kernel<<<NB * NG, 256>>>(x, gn_gamma, gn_beta);
  prep_w_kernel<<<(OC3 * NC + NC * NC) / 4 / 256, 256>>>(qkv_w, proj_w);
  gemm_bf16_kernel<OC3, true><<<dim3(8, 12, NB), 256, GEMM_SMEM>>>(
      wqh, wql, qkv_b, xnh, xnl, nullptr, nullptr, qh, qlo);
  attn_mma_kernel<<<dim3(4, NB * NHEADS), 256, ATT_SMEM>>>(qh, qlo, ath, atl);
  gemm_bf16_kernel<NC, false><<<dim3(8, 4, NB), 256, GEMM_SMEM>>>(
      wph, wpl, proj_b, ath, atl, x, out, nullptr, nullptr);
}

// round 12
// speedup vs baseline: 1.5643x; 1.5643x over previous
#include <cuda_runtime.h>
#include <math.h>
#include <stdint.h>

#define NB 16
#define NC 512
#define NHW 1024
#define NHEADS 8
#define HD 64
#define NG 32
#define OC3 1536
#define GN_EPS 1e-5f

typedef unsigned short ushort_t;

// Scratch (static device globals — allocation-free per harness rules)
__device__ ushort_t g_wqhi[(size_t)OC3 * NC];
__device__ ushort_t g_wqlo[(size_t)OC3 * NC];
__device__ ushort_t g_wphi[(size_t)NC * NC];
__device__ ushort_t g_wplo[(size_t)NC * NC];
__device__ ushort_t g_xnhi[(size_t)NB * NC * NHW];
__device__ ushort_t g_xnlo[(size_t)NB * NC * NHW];
__device__ ushort_t g_qkvhi[(size_t)NB * OC3 * NHW];
__device__ ushort_t g_qkvlo[(size_t)NB * OC3 * NHW];
__device__ ushort_t g_atthi[(size_t)NB * NC * NHW];
__device__ ushort_t g_attlo[(size_t)NB * NC * NHW];

// ============================ helpers ======================================
__device__ __forceinline__ uint32_t smem_u32(const void* p) {
  uint32_t a;
  asm("{ .reg .u64 t; cvta.to.shared.u64 t, %1; cvt.u32.u64 %0, t; }"
      : "=r"(a) : "l"(p));
  return a;
}
__device__ __forceinline__ uint32_t packbf2(float lo16, float hi16) {
  uint32_t r;
  asm("cvt.rn.bf16x2.f32 %0, %1, %2;" : "=r"(r) : "f"(hi16), "f"(lo16));
  return r;
}
__device__ __forceinline__ float bflo_f(uint32_t u) {
  return __uint_as_float(u << 16);
}
__device__ __forceinline__ float bfhi_f(uint32_t u) {
  return __uint_as_float(u & 0xffff0000u);
}
__device__ __forceinline__ float ex2f(float x) {
  float r;
  asm("ex2.approx.ftz.f32 %0, %1;" : "=f"(r) : "f"(x));
  return r;
}
__device__ __forceinline__ void ldsm_x4(uint32_t* r, uint32_t addr) {
  asm volatile("ldmatrix.sync.aligned.m8n8.x4.shared.b16 {%0,%1,%2,%3}, [%4];"
               : "=r"(r[0]), "=r"(r[1]), "=r"(r[2]), "=r"(r[3]) : "r"(addr));
}
__device__ __forceinline__ void ldsm_x4_t(uint32_t* r, uint32_t addr) {
  asm volatile(
      "ldmatrix.sync.aligned.m8n8.x4.trans.shared.b16 {%0,%1,%2,%3}, [%4];"
      : "=r"(r[0]), "=r"(r[1]), "=r"(r[2]), "=r"(r[3]) : "r"(addr));
}
__device__ __forceinline__ void mma16816(float* d, const uint32_t* a,
                                         const uint32_t* b) {
  asm volatile(
      "mma.sync.aligned.m16n8k16.row.col.f32.bf16.bf16.f32 "
      "{%0,%1,%2,%3}, {%4,%5,%6,%7}, {%8,%9}, {%0,%1,%2,%3};"
      : "+f"(d[0]), "+f"(d[1]), "+f"(d[2]), "+f"(d[3])
      : "r"(a[0]), "r"(a[1]), "r"(a[2]), "r"(a[3]), "r"(b[0]), "r"(b[1]));
}
__device__ __forceinline__ void cp_async16(uint32_t dst, const void* src) {
  asm volatile("cp.async.cg.shared.global [%0], [%1], 16;" :: "r"(dst),
               "l"(src));
}
#define CP_COMMIT() asm volatile("cp.async.commit_group;" ::: "memory")
#define CP_WAIT(n) asm volatile("cp.async.wait_group %0;" :: "n"(n) : "memory")

// ---------------------------------------------------------------------------
// Weight prep: fp32 -> hi/lo bf16 planes (once per launch)
// ---------------------------------------------------------------------------
__global__ void __launch_bounds__(256) prep_w_kernel(
    const float* __restrict__ qkv_w, const float* __restrict__ proj_w) {
  const int idx = blockIdx.x * 256 + threadIdx.x;
  const int nq = OC3 * NC / 4;
  const float* src;
  ushort_t *dh, *dl;
  int off;
  if (idx < nq) {
    src = qkv_w; dh = g_wqhi; dl = g_wqlo; off = idx * 4;
  } else {
    src = proj_w; dh = g_wphi; dl = g_wplo; off = (idx - nq) * 4;
  }
  float4 v = *(const float4*)(src + off);
  uint32_t h01 = packbf2(v.x, v.y), h23 = packbf2(v.z, v.w);
  uint32_t l01 = packbf2(v.x - bflo_f(h01), v.y - bfhi_f(h01));
  uint32_t l23 = packbf2(v.z - bflo_f(h23), v.w - bfhi_f(h23));
  *(uint2*)(dh + off) = make_uint2(h01, h23);
  *(uint2*)(dl + off) = make_uint2(l01, l23);
}

// ---------------------------------------------------------------------------
// GroupNorm -> hi/lo bf16 planes
// ---------------------------------------------------------------------------
__global__ void __launch_bounds__(256) gn_kernel(
    const float* __restrict__ x, const float* __restrict__ gamma,
    const float* __restrict__ beta) {
  const int bg = blockIdx.x;
  const int g = bg & (NG - 1);
  const size_t base = (size_t)bg * (NC / NG) * NHW;
  const float* px = x + base;
  ushort_t* poh = g_xnhi + base;
  ushort_t* pol = g_xnlo + base;
  const int tid = threadIdx.x;

  float s = 0.f, q = 0.f;
#pragma unroll
  for (int k = 0; k < 16; k++) {
    float4 v = *(const float4*)(px + (size_t)(tid + k * 256) * 4);
    s += v.x + v.y + v.z + v.w;
    q += v.x * v.x + v.y * v.y + v.z * v.z + v.w * v.w;
  }
#pragma unroll
  for (int off = 16; off; off >>= 1) {
    s += __shfl_xor_sync(0xffffffffu, s, off);
    q += __shfl_xor_sync(0xffffffffu, q, off);
  }
  __shared__ float ss[8], sq[8];
  __shared__ float s_mean, s_inv;
  const int w = tid >> 5;
  if ((tid & 31) == 0) { ss[w] = s; sq[w] = q; }
  __syncthreads();
  if (tid == 0) {
    float ts = 0.f, tq = 0.f;
#pragma unroll
    for (int i = 0; i < 8; i++) { ts += ss[i]; tq += sq[i]; }
    float mean = ts * (1.f / 16384.f);
    float var = tq * (1.f / 16384.f) - mean * mean;
    s_mean = mean;
    s_inv = rsqrtf(var + GN_EPS);
  }
  __syncthreads();
  const float mean = s_mean, inv = s_inv;
#pragma unroll
  for (int k = 0; k < 16; k++) {
    size_t off = (size_t)(tid + k * 256) * 4;
    int c = g * 16 + (int)(off >> 10);
    float ga = gamma[c], be = beta[c];
    float4 v = *(const float4*)(px + off);
    v.x = (v.x - mean) * inv * ga + be;
    v.y = (v.y - mean) * inv * ga + be;
    v.z = (v.z - mean) * inv * ga + be;
    v.w = (v.w - mean) * inv * ga + be;
    uint32_t h01 = packbf2(v.x, v.y), h23 = packbf2(v.z, v.w);
    uint32_t l01 = packbf2(v.x - bflo_f(h01), v.y - bfhi_f(h01));
    uint32_t l23 = packbf2(v.z - bflo_f(h23), v.w - bfhi_f(h23));
    *(uint2*)(poh + off) = make_uint2(h01, h23);
    *(uint2*)(pol + off) = make_uint2(l01, l23);
  }
}

// ---------------------------------------------------------------------------
// bf16 GEMM (3-term split), cp.async double-buffered smem (zero register
// footprint for copies — avoids R9/R10 spills). R8's known-good MMA body.
// Tile 128(o) x 128(t), K-chunk 32; 8 warps = 4m x 2n; warp 32x64.
// ---------------------------------------------------------------------------
#define SAH 40
#define SBH 136
#define A_ELE (2 * 128 * SAH)
#define B_ELE (2 * 32 * SBH)
#define BUF_ELE (A_ELE + B_ELE)
#define GEMM_SMEM (2 * BUF_ELE * (int)sizeof(ushort_t))
#define NCH (NC / 32)

template <int OC, bool EMIT>
__global__ void __launch_bounds__(256) gemm_bf16_kernel(
    const ushort_t* __restrict__ Ahi, const ushort_t* __restrict__ Alo,
    const float* __restrict__ bias, const ushort_t* __restrict__ Bhi,
    const ushort_t* __restrict__ Blo, const float* __restrict__ R,
    float* __restrict__ Yf, ushort_t* __restrict__ Yhi,
    ushort_t* __restrict__ Ylo) {
  extern __shared__ __align__(16) ushort_t smem[];

  const int tid = threadIdx.x, lane = tid & 31, wid = tid >> 5;
  const int wm = wid >> 1, wn = wid & 1;
  const int bz = blockIdx.z;
  const int o0 = blockIdx.y * 128;
  const int t0 = blockIdx.x * 128;
  const size_t bb = (size_t)bz * NC * NHW;

  const int a_r = lane & 15, a_c = (lane >> 4) << 3;
  const int b_g = lane >> 3;
  const int b_row = ((b_g & 1) << 3) + (lane & 7);
  const int b_col = (b_g >> 1) << 3;

  float acc[2][8][4] = {};

#define CP_CHUNK(kc, buf)                                                    \
  {                                                                          \
    ushort_t* Asm = smem + (buf)*BUF_ELE;                                    \
    ushort_t* Bsm = Asm + A_ELE;                                             \
    _Pragma("unroll") for (int i = 0; i < 4; i++) {                          \
      const int idx = i * 256 + tid;                                         \
      const int pl = idx >> 9, r = (idx >> 2) & 127, cc = idx & 3;           \
      cp_async16(smem_u32(&Asm[pl * 128 * SAH + r * SAH + cc * 8]),          \
                 (pl ? Alo : Ahi) + (size_t)(o0 + r) * NC + (kc) + cc * 8);  \
    }                                                                        \
    _Pragma("unroll") for (int i = 0; i < 4; i++) {                          \
      const int idx = i * 256 + tid;                                         \
      const int pl = idx >> 9, r = (idx >> 4) & 31, cc = idx & 15;           \
      cp_async16(smem_u32(&Bsm[pl * 32 * SBH + r * SBH + cc * 8]),           \
                 (pl ? Blo : Bhi) + bb + (size_t)((kc) + r) * NHW + t0 +     \
                     cc * 8);                                                \
    }                                                                        \
  }

  CP_CHUNK(0, 0);
  CP_COMMIT();

#pragma unroll 1
  for (int chunk = 0; chunk < NCH; chunk++) {
    const int cur = chunk & 1;
    __syncthreads();  // all warps done reading buffer cur^1 (prev chunk)
    if (chunk < NCH - 1) {
      CP_CHUNK((chunk + 1) * 32, cur ^ 1);
      CP_COMMIT();
      CP_WAIT(1);  // chunk's group complete (only chunk+1's outstanding)
    } else {
      CP_WAIT(0);
    }
    __syncthreads();  // everyone's cp.async data visible

    const ushort_t* Asm = smem + cur * BUF_ELE;
    const ushort_t* Bsm = Asm + A_ELE;
#pragma unroll
    for (int ks = 0; ks < 2; ks++) {
      const int kb = ks * 16;
      uint32_t ah[2][4], al[2][4];
#pragma unroll
      for (int mf = 0; mf < 2; mf++) {
        const int ao = (wm * 32 + mf * 16 + a_r) * SAH + kb + a_c;
        ldsm_x4(ah[mf], smem_u32(&Asm[ao]));
        ldsm_x4(al[mf], smem_u32(&Asm[128 * SAH + ao]));
      }
#pragma unroll
      for (int nb = 0; nb < 4; nb++) {
        uint32_t bh[4], bl[4];
        const int bo = (kb + b_row) * SBH + wn * 64 + nb * 16 + b_col;
        ldsm_x4_t(bh, smem_u32(&Bsm[bo]));
        ldsm_x4_t(bl, smem_u32(&Bsm[32 * SBH + bo]));
#pragma unroll
        for (int mf = 0; mf < 2; mf++) {
          mma16816(acc[mf][2 * nb], ah[mf], &bh[0]);
          mma16816(acc[mf][2 * nb + 1], ah[mf], &bh[2]);
          mma16816(acc[mf][2 * nb], ah[mf], &bl[0]);
          mma16816(acc[mf][2 * nb + 1], ah[mf], &bl[2]);
          mma16816(acc[mf][2 * nb], al[mf], &bh[0]);
          mma16816(acc[mf][2 * nb + 1], al[mf], &bh[2]);
        }
      }
    }
  }
#undef CP_CHUNK

#pragma unroll
  for (int mf = 0; mf < 2; mf++)
#pragma unroll
    for (int nf = 0; nf < 8; nf++) {
      const int o = o0 + wm * 32 + mf * 16 + (lane >> 2);
      const int t = t0 + wn * 64 + nf * 8 + ((lane & 3) << 1);
      const size_t off0 = ((size_t)bz * OC + o) * NHW + t;
      const size_t off1 = off0 + (size_t)8 * NHW;
      const float bi0 = bias[o], bi1 = bias[o + 8];
      float y0 = acc[mf][nf][0] + bi0, y1 = acc[mf][nf][1] + bi0;
      float y2 = acc[mf][nf][2] + bi1, y3 = acc[mf][nf][3] + bi1;
      if (EMIT) {
        uint32_t h01 = packbf2(y0, y1), h23 = packbf2(y2, y3);
        uint32_t l01 = packbf2(y0 - bflo_f(h01), y1 - bfhi_f(h01));
        uint32_t l23 = packbf2(y2 - bflo_f(h23), y3 - bfhi_f(h23));
        *(uint32_t*)(Yhi + off0) = h01;
        *(uint32_t*)(Yhi + off1) = h23;
        *(uint32_t*)(Ylo + off0) = l01;
        *(uint32_t*)(Ylo + off1) = l23;
      } else {
        float2 r0 = *(const float2*)(R + off0);
        float2 r1 = *(const float2*)(R + off1);
        *(float2*)(Yf + off0) = make_float2(y0 + r0.x, y1 + r0.y);
        *(float2*)(Yf + off1) = make_float2(y2 + r1.x, y3 + r1.y);
      }
    }
}

// ---------------------------------------------------------------------------
// Flash attention, m32 warp tiles (R9 structure verbatim — 357us measured),
// softmax in base-2 (ex2.approx), scale folded: c = 0.125*log2(e).
// ---------------------------------------------------------------------------
#define SQH 264
#define AQH 136
#define AVH 72
#define SM_SCALE_LOG2 0.1803368801f

__global__ void __launch_bounds__(256) attn_mma_kernel(
    const ushort_t* __restrict__ qkvhi, const ushort_t* __restrict__ qkvlo,
    ushort_t* __restrict__ outhi, ushort_t* __restrict__ outlo) {
  extern __shared__ __align__(16) ushort_t smem[];
  ushort_t* Qh = smem;
  ushort_t* Ql = Qh + 64 * SQH;
  ushort_t* Kh = Ql + 64 * SQH;
  ushort_t* Kl = Kh + 64 * AQH;
  ushort_t* Vh = Kl + 64 * AQH;
  ushort_t* Vl = Vh + 128 * AVH;

  const int tid = threadIdx.x, lane = tid & 31, warp = tid >> 5;
  const int bh_ = blockIdx.y;
  const int b = bh_ >> 3, h = bh_ & 7;
  const int t0 = blockIdx.x * 256;

  const ushort_t* qhp = qkvhi + ((size_t)b * OC3 + h * HD) * NHW;
  const ushort_t* qlp = qkvlo + ((size_t)b * OC3 + h * HD) * NHW;
  const ushort_t* khp = qhp + (size_t)NC * NHW;
  const ushort_t* klp = qlp + (size_t)NC * NHW;
  const ushort_t* vhp = qhp + (size_t)2 * NC * NHW;
  const ushort_t* vlp = qlp + (size_t)2 * NC * NHW;

#pragma unroll
  for (int i = 0; i < 16; i++) {
    const int idx = i * 256 + tid;
    const int pl = idx >> 11, r = (idx >> 5) & 63, c = idx & 31;
    ushort_t* dst = (pl ? Ql : Qh) + r * SQH + c * 8;
    const ushort_t* src = (pl ? qlp : qhp) + (size_t)r * NHW + t0 + c * 8;
    *(uint4*)dst = *(const uint4*)src;
  }
  __syncthreads();

  const int a_kr = ((lane >> 4) << 3) + (lane & 7);
  const int a_mc = ((lane >> 3) & 1) << 3;
  const int b_g = lane >> 3;
  const int b_row = ((b_g & 1) << 3) + (lane & 7);
  const int b_col = (b_g >> 1) << 3;

  uint32_t aq[2][4][4];
#pragma unroll
  for (int mf = 0; mf < 2; mf++)
#pragma unroll
    for (int k4 = 0; k4 < 4; k4++) {
      const int ao = (k4 * 16 + a_kr) * SQH + warp * 32 + mf * 16 + a_mc;
      ldsm_x4_t(aq[mf][k4], smem_u32(&Qh[ao]));
    }

  float o8[2][8][4] = {};
  float mM[2][2], lL[2][2];
#pragma unroll
  for (int mf = 0; mf < 2; mf++) {
    mM[mf][0] = -1e30f; mM[mf][1] = -1e30f;
    lL[mf][0] = 0.f; lL[mf][1] = 0.f;
  }

#pragma unroll 1
  for (int s0 = 0; s0 < NHW; s0 += 128) {
#pragma unroll
    for (int i = 0; i < 8; i++) {
      const int idx = i * 256 + tid;
      const int pl = idx >> 10, r = (idx >> 4) & 63, c = idx & 15;
      ushort_t* dst = (pl ? Kl : Kh) + r * AQH + c * 8;
      const ushort_t* src = (pl ? klp : khp) + (size_t)r * NHW + s0 + c * 8;
      *(uint4*)dst = *(const uint4*)src;
    }
#pragma unroll
    for (int i = 0; i < 4; i++) {
      const int idx = i * 256 + tid;
      const int pl = idx >> 9, u = idx & 511;
      const int dp = u & 31, sc = u >> 5;
      const ushort_t* src = pl ? vlp : vhp;
      ushort_t* dst = pl ? Vl : Vh;
      uint4 r0 = *(const uint4*)(src + (size_t)(2 * dp) * NHW + s0 + sc * 8);
      uint4 r1 =
          *(const uint4*)(src + (size_t)(2 * dp + 1) * NHW + s0 + sc * 8);
      uint32_t q0[4] = {r0.x, r0.y, r0.z, r0.w};
      uint32_t q1[4] = {r1.x, r1.y, r1.z, r1.w};
#pragma unroll
      for (int j2 = 0; j2 < 4; j2++) {
        uint32_t a = q0[j2], bq = q1[j2];
        uint32_t w0 = (a & 0xffffu) | (bq << 16);
        uint32_t w1 = (a >> 16) | (bq & 0xffff0000u);
        const int s = sc * 8 + 2 * j2;
        *(uint32_t*)&dst[s * AVH + 2 * dp] = w0;
        *(uint32_t*)&dst[(s + 1) * AVH + 2 * dp] = w1;
      }
    }
    __syncthreads();

#pragma unroll
    for (int hf = 0; hf < 2; hf++) {
      uint32_t aql[2][4][4];
#pragma unroll
      for (int mf = 0; mf < 2; mf++)
#pragma unroll
        for (int k4 = 0; k4 < 4; k4++) {
          const int ao = (k4 * 16 + a_kr) * SQH + warp * 32 + mf * 16 + a_mc;
          ldsm_x4_t(aql[mf][k4], smem_u32(&Ql[ao]));
        }

      float sacc[2][8][4] = {};
#pragma unroll
      for (int k4 = 0; k4 < 4; k4++) {
#pragma unroll
        for (int nb = 0; nb < 4; nb++) {
          uint32_t kbh[4], kbl[4];
          const int bo = (k4 * 16 + b_row) * AQH + hf * 64 + nb * 16 + b_col;
          ldsm_x4_t(kbh, smem_u32(&Kh[bo]));
          ldsm_x4_t(kbl, smem_u32(&Kl[bo]));
#pragma unroll
          for (int mf = 0; mf < 2; mf++) {
            mma16816(sacc[mf][2 * nb], aq[mf][k4], &kbh[0]);
            mma16816(sacc[mf][2 * nb + 1], aq[mf][k4], &kbh[2]);
            mma16816(sacc[mf][2 * nb], aq[mf][k4], &kbl[0]);
            mma16816(sacc[mf][2 * nb + 1], aq[mf][k4], &kbl[2]);
            mma16816(sacc[mf][2 * nb], aql[mf][k4], &kbh[0]);
            mma16816(sacc[mf][2 * nb + 1], aql[mf][k4], &kbh[2]);
          }
        }
      }

      // ---- online softmax (base-2) + pack P ----
      uint32_t Ph[2][4][4], Pw[2][4][4];
#pragma unroll
      for (int mf = 0; mf < 2; mf++) {
        float mt0 = -1e30f, mt1 = -1e30f;
#pragma unroll
        for (int f = 0; f < 8; f++) {
          sacc[mf][f][0] *= SM_SCALE_LOG2;
          sacc[mf][f][1] *= SM_SCALE_LOG2;
          sacc[mf][f][2] *= SM_SCALE_LOG2;
          sacc[mf][f][3] *= SM_SCALE_LOG2;
          mt0 = fmaxf(mt0, fmaxf(sacc[mf][f][0], sacc[mf][f][1]));
          mt1 = fmaxf(mt1, fmaxf(sacc[mf][f][2], sacc[mf][f][3]));
        }
        mt0 = fmaxf(mt0, __shfl_xor_sync(0xffffffffu, mt0, 1));
        mt0 = fmaxf(mt0, __shfl_xor_sync(0xffffffffu, mt0, 2));
        mt1 = fmaxf(mt1, __shfl_xor_sync(0xffffffffu, mt1, 1));
        mt1 = fmaxf(mt1, __shfl_xor_sync(0xffffffffu, mt1, 2));
        const float mn0 = fmaxf(mM[mf][0], mt0);
        const float mn1 = fmaxf(mM[mf][1], mt1);
        const float fac0 = ex2f(mM[mf][0] - mn0);
        const float fac1 = ex2f(mM[mf][1] - mn1);
        mM[mf][0] = mn0; mM[mf][1] = mn1;
        float rs0 = 0.f, rs1 = 0.f;
#pragma unroll
        for (int f = 0; f < 8; f++) {
          sacc[mf][f][0] = ex2f(sacc[mf][f][0] - mn0);
          sacc[mf][f][1] = ex2f(sacc[mf][f][1] - mn0);
          sacc[mf][f][2] = ex2f(sacc[mf][f][2] - mn1);
          sacc[mf][f][3] = ex2f(sacc[mf][f][3] - mn1);
          rs0 += sacc[mf][f][0] + sacc[mf][f][1];
          rs1 += sacc[mf][f][2] + sacc[mf][f][3];
        }
        rs0 += __shfl_xor_sync(0xffffffffu, rs0, 1);
        rs0 += __shfl_xor_sync(0xffffffffu, rs0, 2);
        rs1 += __shfl_xor_sync(0xffffffffu, rs1, 1);
        rs1 += __shfl_xor_sync(0xffffffffu, rs1, 2);
        lL[mf][0] = lL[mf][0] * fac0 + rs0;
        lL[mf][1] = lL[mf][1] * fac1 + rs1;
#pragma unroll
        for (int f = 0; f < 8; f++) {
          o8[mf][f][0] *= fac0; o8[mf][f][1] *= fac0;
          o8[mf][f][2] *= fac1; o8[mf][f][3] *= fac1;
        }
#pragma unroll
        for (int f = 0; f < 8; f++) {
          const int k8 = f >> 1, sl = (f & 1) << 1;
          uint32_t h01 = packbf2(sacc[mf][f][0], sacc[mf][f][1]);
          uint32_t h23 = packbf2(sacc[mf][f][2], sacc[mf][f][3]);
          Ph[mf][k8][sl] = h01;
          Ph[mf][k8][sl + 1] = h23;
          Pw[mf][k8][sl] = packbf2(sacc[mf][f][0] - bflo_f(h01),
                                   sacc[mf][f][1] - bfhi_f(h01));
          Pw[mf][k8][sl + 1] = packbf2(sacc[mf][f][2] - bflo_f(h23),
                                       sacc[mf][f][3] - bfhi_f(h23));
        }
      }

      // ---- O += P V ----
#pragma unroll
      for (int k8 = 0; k8 < 4; k8++) {
#pragma unroll
        for (int nb = 0; nb < 4; nb++) {
          uint32_t vh[4], vl[4];
          const int vo = (hf * 64 + k8 * 16 + b_row) * AVH + nb * 16 + b_col;
          ldsm_x4_t(vh, smem_u32(&Vh[vo]));
          ldsm_x4_t(vl, smem_u32(&Vl[vo]));
#pragma unroll
          for (int mf = 0; mf < 2; mf++) {
            mma16816(o8[mf][2 * nb], Ph[mf][k8], &vh[0]);
            mma16816(o8[mf][2 * nb + 1], Ph[mf][k8], &vh[2]);
            mma16816(o8[mf][2 * nb], Ph[mf][k8], &vl[0]);
            mma16816(o8[mf][2 * nb + 1], Ph[mf][k8], &vl[2]);
            mma16816(o8[mf][2 * nb], Pw[mf][k8], &vh[0]);
            mma16816(o8[mf][2 * nb + 1], Pw[mf][k8], &vh[2]);
          }
        }
      }
    }
    __syncthreads();
  }

  // ---- epilogue ----
  float* Ost = (float*)Qh;
  const float i00 = 1.f / lL[0][0], i01 = 1.f / lL[0][1];
  const float i10 = 1.f / lL[1][0], i11 = 1.f / lL[1][1];
#pragma unroll
  for (int mf = 0; mf < 2; mf++) {
    const float iv0 = mf ? i10 : i00, iv1 = mf ? i11 : i01;
    const int t = warp * 32 + mf * 16 + (lane >> 2);
#pragma unroll
    for (int f = 0; f < 8; f++) {
      const int d = f * 8 + ((lane & 3) << 1);
      Ost[d * 260 + t] = o8[mf][f][0] * iv0;
      Ost[(d + 1) * 260 + t] = o8[mf][f][1] * iv0;
      Ost[d * 260 + t + 8] = o8[mf][f][2] * iv1;
      Ost[(d + 1) * 260 + t + 8] = o8[mf][f][3] * iv1;
    }
  }
  __syncthreads();
#pragma unroll
  for (int i = 0; i < 8; i++) {
    const int idx = i * 256 + tid;
    const int r = idx >> 5, c = idx & 31;
    const float* src = &Ost[r * 260 + c * 8];
    uint32_t hu[4], lu[4];
#pragma unroll
    for (int j = 0; j < 4; j++) {
      float v0 = src[2 * j], v1 = src[2 * j + 1];
      hu[j] = packbf2(v0, v1);
      lu[j] = packbf2(v0 - bflo_f(hu[j]), v1 - bfhi_f(hu[j]));
    }
    const size_t off = ((size_t)b * NC + h * HD + r) * NHW + t0 + c * 8;
    *(uint4*)(outhi + off) = make_uint4(hu[0], hu[1], hu[2], hu[3]);
    *(uint4*)(outlo + off) = make_uint4(lu[0], lu[1], lu[2], lu[3]);
  }
}

// ---------------------------------------------------------------------------
extern "C" void kernel_launch(void* const* d_in, const int* in_sizes, int n_in,
                              void* d_out, int out_size) {
  const float* x = (const float*)d_in[0];
  const float* gn_gamma = (const float*)d_in[1];
  const float* gn_beta = (const float*)d_in[2];
  const float* qkv_w = (const float*)d_in[3];
  const float* qkv_b = (const float*)d_in[4];
  const float* proj_w = (const float*)d_in[5];
  const float* proj_b = (const float*)d_in[6];
  float* out = (float*)d_out;

  ushort_t *wqh, *wql, *wph, *wpl, *xnh, *xnl, *qh, *qlo, *ath, *atl;
  cudaGetSymbolAddress((void**)&wqh, g_wqhi);
  cudaGetSymbolAddress((void**)&wql, g_wqlo);
  cudaGetSymbolAddress((void**)&wph, g_wphi);
  cudaGetSymbolAddress((void**)&wpl, g_wplo);
  cudaGetSymbolAddress((void**)&xnh, g_xnhi);
  cudaGetSymbolAddress((void**)&xnl, g_xnlo);
  cudaGetSymbolAddress((void**)&qh, g_qkvhi);
  cudaGetSymbolAddress((void**)&qlo, g_qkvlo);
  cudaGetSymbolAddress((void**)&ath, g_atthi);
  cudaGetSymbolAddress((void**)&atl, g_attlo);

  const int ATT_SMEM =
      (2 * 64 * SQH + 2 * 64 * AQH + 2 * 128 * AVH) * (int)sizeof(ushort_t);
  cudaFuncSetAttribute(attn_mma_kernel,
                       cudaFuncAttributeMaxDynamicSharedMemorySize, ATT_SMEM);
  cudaFuncSetAttribute(gemm_bf16_kernel<OC3, true>,
                       cudaFuncAttributeMaxDynamicSharedMemorySize, GEMM_SMEM);
  cudaFuncSetAttribute(gemm_bf16_kernel<NC, false>,
                       cudaFuncAttributeMaxDynamicSharedMemorySize, GEMM_SMEM);

  gn_kernel<<<NB * NG, 256>>>(x, gn_gamma, gn_beta);
  prep_w_kernel<<<(OC3 * NC + NC * NC) / 4 / 256, 256>>>(qkv_w, proj_w);
  gemm_bf16_kernel<OC3, true><<<dim3(8, 12, NB), 256, GEMM_SMEM>>>(
      wqh, wql, qkv_b, xnh, xnl, nullptr, nullptr, qh, qlo);
  attn_mma_kernel<<<dim3(4, NB * NHEADS), 256, ATT_SMEM>>>(qh, qlo, ath, atl);
  gemm_bf16_kernel<NC, false><<<dim3(8, 4, NB), 256, GEMM_SMEM>>>(
      wph, wpl, proj_b, ath, atl, x, out, nullptr, nullptr);
}

// round 13
// speedup vs baseline: 1.5776x; 1.0085x over previous
#include <cuda_runtime.h>
#include <math.h>
#include <stdint.h>

#define NB 16
#define NC 512
#define NHW 1024
#define NHEADS 8
#define HD 64
#define NG 32
#define OC3 1536
#define GN_EPS 1e-5f

typedef unsigned short ushort_t;

// Scratch (static device globals — allocation-free per harness rules)
__device__ ushort_t g_wqhi[(size_t)OC3 * NC];
__device__ ushort_t g_wqlo[(size_t)OC3 * NC];
__device__ ushort_t g_wphi[(size_t)NC * NC];
__device__ ushort_t g_wplo[(size_t)NC * NC];
__device__ ushort_t g_xnhi[(size_t)NB * NC * NHW];
__device__ ushort_t g_xnlo[(size_t)NB * NC * NHW];
__device__ ushort_t g_qkvhi[(size_t)NB * OC3 * NHW];
__device__ ushort_t g_qkvlo[(size_t)NB * OC3 * NHW];
__device__ ushort_t g_atthi[(size_t)NB * NC * NHW];
__device__ ushort_t g_attlo[(size_t)NB * NC * NHW];

// ============================ helpers ======================================
__device__ __forceinline__ uint32_t smem_u32(const void* p) {
  uint32_t a;
  asm("{ .reg .u64 t; cvta.to.shared.u64 t, %1; cvt.u32.u64 %0, t; }"
      : "=r"(a) : "l"(p));
  return a;
}
__device__ __forceinline__ uint32_t packbf2(float lo16, float hi16) {
  uint32_t r;
  asm("cvt.rn.bf16x2.f32 %0, %1, %2;" : "=r"(r) : "f"(hi16), "f"(lo16));
  return r;
}
__device__ __forceinline__ float bflo_f(uint32_t u) {
  return __uint_as_float(u << 16);
}
__device__ __forceinline__ float bfhi_f(uint32_t u) {
  return __uint_as_float(u & 0xffff0000u);
}
__device__ __forceinline__ float ex2f(float x) {
  float r;
  asm("ex2.approx.ftz.f32 %0, %1;" : "=f"(r) : "f"(x));
  return r;
}
__device__ __forceinline__ void ldsm_x4(uint32_t* r, uint32_t addr) {
  asm volatile("ldmatrix.sync.aligned.m8n8.x4.shared.b16 {%0,%1,%2,%3}, [%4];"
               : "=r"(r[0]), "=r"(r[1]), "=r"(r[2]), "=r"(r[3]) : "r"(addr));
}
__device__ __forceinline__ void ldsm_x4_t(uint32_t* r, uint32_t addr) {
  asm volatile(
      "ldmatrix.sync.aligned.m8n8.x4.trans.shared.b16 {%0,%1,%2,%3}, [%4];"
      : "=r"(r[0]), "=r"(r[1]), "=r"(r[2]), "=r"(r[3]) : "r"(addr));
}
__device__ __forceinline__ void mma16816(float* d, const uint32_t* a,
                                         const uint32_t* b) {
  asm volatile(
      "mma.sync.aligned.m16n8k16.row.col.f32.bf16.bf16.f32 "
      "{%0,%1,%2,%3}, {%4,%5,%6,%7}, {%8,%9}, {%0,%1,%2,%3};"
      : "+f"(d[0]), "+f"(d[1]), "+f"(d[2]), "+f"(d[3])
      : "r"(a[0]), "r"(a[1]), "r"(a[2]), "r"(a[3]), "r"(b[0]), "r"(b[1]));
}
__device__ __forceinline__ void cp_async16(uint32_t dst, const void* src) {
  asm volatile("cp.async.cg.shared.global [%0], [%1], 16;" :: "r"(dst),
               "l"(src));
}
#define CP_COMMIT() asm volatile("cp.async.commit_group;" ::: "memory")
#define CP_WAIT(n) asm volatile("cp.async.wait_group %0;" :: "n"(n) : "memory")

// ---------------------------------------------------------------------------
// Weight prep: fp32 -> hi/lo bf16 planes (once per launch)
// ---------------------------------------------------------------------------
__global__ void __launch_bounds__(256) prep_w_kernel(
    const float* __restrict__ qkv_w, const float* __restrict__ proj_w) {
  const int idx = blockIdx.x * 256 + threadIdx.x;
  const int nq = OC3 * NC / 4;
  const float* src;
  ushort_t *dh, *dl;
  int off;
  if (idx < nq) {
    src = qkv_w; dh = g_wqhi; dl = g_wqlo; off = idx * 4;
  } else {
    src = proj_w; dh = g_wphi; dl = g_wplo; off = (idx - nq) * 4;
  }
  float4 v = *(const float4*)(src + off);
  uint32_t h01 = packbf2(v.x, v.y), h23 = packbf2(v.z, v.w);
  uint32_t l01 = packbf2(v.x - bflo_f(h01), v.y - bfhi_f(h01));
  uint32_t l23 = packbf2(v.z - bflo_f(h23), v.w - bfhi_f(h23));
  *(uint2*)(dh + off) = make_uint2(h01, h23);
  *(uint2*)(dl + off) = make_uint2(l01, l23);
}

// ---------------------------------------------------------------------------
// GroupNorm -> hi/lo bf16 planes
// ---------------------------------------------------------------------------
__global__ void __launch_bounds__(256) gn_kernel(
    const float* __restrict__ x, const float* __restrict__ gamma,
    const float* __restrict__ beta) {
  const int bg = blockIdx.x;
  const int g = bg & (NG - 1);
  const size_t base = (size_t)bg * (NC / NG) * NHW;
  const float* px = x + base;
  ushort_t* poh = g_xnhi + base;
  ushort_t* pol = g_xnlo + base;
  const int tid = threadIdx.x;

  float s = 0.f, q = 0.f;
#pragma unroll
  for (int k = 0; k < 16; k++) {
    float4 v = *(const float4*)(px + (size_t)(tid + k * 256) * 4);
    s += v.x + v.y + v.z + v.w;
    q += v.x * v.x + v.y * v.y + v.z * v.z + v.w * v.w;
  }
#pragma unroll
  for (int off = 16; off; off >>= 1) {
    s += __shfl_xor_sync(0xffffffffu, s, off);
    q += __shfl_xor_sync(0xffffffffu, q, off);
  }
  __shared__ float ss[8], sq[8];
  __shared__ float s_mean, s_inv;
  const int w = tid >> 5;
  if ((tid & 31) == 0) { ss[w] = s; sq[w] = q; }
  __syncthreads();
  if (tid == 0) {
    float ts = 0.f, tq = 0.f;
#pragma unroll
    for (int i = 0; i < 8; i++) { ts += ss[i]; tq += sq[i]; }
    float mean = ts * (1.f / 16384.f);
    float var = tq * (1.f / 16384.f) - mean * mean;
    s_mean = mean;
    s_inv = rsqrtf(var + GN_EPS);
  }
  __syncthreads();
  const float mean = s_mean, inv = s_inv;
#pragma unroll
  for (int k = 0; k < 16; k++) {
    size_t off = (size_t)(tid + k * 256) * 4;
    int c = g * 16 + (int)(off >> 10);
    float ga = gamma[c], be = beta[c];
    float4 v = *(const float4*)(px + off);
    v.x = (v.x - mean) * inv * ga + be;
    v.y = (v.y - mean) * inv * ga + be;
    v.z = (v.z - mean) * inv * ga + be;
    v.w = (v.w - mean) * inv * ga + be;
    uint32_t h01 = packbf2(v.x, v.y), h23 = packbf2(v.z, v.w);
    uint32_t l01 = packbf2(v.x - bflo_f(h01), v.y - bfhi_f(h01));
    uint32_t l23 = packbf2(v.z - bflo_f(h23), v.w - bfhi_f(h23));
    *(uint2*)(poh + off) = make_uint2(h01, h23);
    *(uint2*)(pol + off) = make_uint2(l01, l23);
  }
}

// ---------------------------------------------------------------------------
// bf16 GEMM (3-term split), cp.async double-buffered smem (R12 verbatim).
// ---------------------------------------------------------------------------
#define SAH 40
#define SBH 136
#define A_ELE (2 * 128 * SAH)
#define B_ELE (2 * 32 * SBH)
#define BUF_ELE (A_ELE + B_ELE)
#define GEMM_SMEM (2 * BUF_ELE * (int)sizeof(ushort_t))
#define NCH (NC / 32)

template <int OC, bool EMIT>
__global__ void __launch_bounds__(256) gemm_bf16_kernel(
    const ushort_t* __restrict__ Ahi, const ushort_t* __restrict__ Alo,
    const float* __restrict__ bias, const ushort_t* __restrict__ Bhi,
    const ushort_t* __restrict__ Blo, const float* __restrict__ R,
    float* __restrict__ Yf, ushort_t* __restrict__ Yhi,
    ushort_t* __restrict__ Ylo) {
  extern __shared__ __align__(16) ushort_t smem[];

  const int tid = threadIdx.x, lane = tid & 31, wid = tid >> 5;
  const int wm = wid >> 1, wn = wid & 1;
  const int bz = blockIdx.z;
  const int o0 = blockIdx.y * 128;
  const int t0 = blockIdx.x * 128;
  const size_t bb = (size_t)bz * NC * NHW;

  const int a_r = lane & 15, a_c = (lane >> 4) << 3;
  const int b_g = lane >> 3;
  const int b_row = ((b_g & 1) << 3) + (lane & 7);
  const int b_col = (b_g >> 1) << 3;

  float acc[2][8][4] = {};

#define CP_CHUNK(kc, buf)                                                    \
  {                                                                          \
    ushort_t* Asm = smem + (buf)*BUF_ELE;                                    \
    ushort_t* Bsm = Asm + A_ELE;                                             \
    _Pragma("unroll") for (int i = 0; i < 4; i++) {                          \
      const int idx = i * 256 + tid;                                         \
      const int pl = idx >> 9, r = (idx >> 2) & 127, cc = idx & 3;           \
      cp_async16(smem_u32(&Asm[pl * 128 * SAH + r * SAH + cc * 8]),          \
                 (pl ? Alo : Ahi) + (size_t)(o0 + r) * NC + (kc) + cc * 8);  \
    }                                                                        \
    _Pragma("unroll") for (int i = 0; i < 4; i++) {                          \
      const int idx = i * 256 + tid;                                         \
      const int pl = idx >> 9, r = (idx >> 4) & 31, cc = idx & 15;           \
      cp_async16(smem_u32(&Bsm[pl * 32 * SBH + r * SBH + cc * 8]),           \
                 (pl ? Blo : Bhi) + bb + (size_t)((kc) + r) * NHW + t0 +     \
                     cc * 8);                                                \
    }                                                                        \
  }

  CP_CHUNK(0, 0);
  CP_COMMIT();

#pragma unroll 1
  for (int chunk = 0; chunk < NCH; chunk++) {
    const int cur = chunk & 1;
    __syncthreads();
    if (chunk < NCH - 1) {
      CP_CHUNK((chunk + 1) * 32, cur ^ 1);
      CP_COMMIT();
      CP_WAIT(1);
    } else {
      CP_WAIT(0);
    }
    __syncthreads();

    const ushort_t* Asm = smem + cur * BUF_ELE;
    const ushort_t* Bsm = Asm + A_ELE;
#pragma unroll
    for (int ks = 0; ks < 2; ks++) {
      const int kb = ks * 16;
      uint32_t ah[2][4], al[2][4];
#pragma unroll
      for (int mf = 0; mf < 2; mf++) {
        const int ao = (wm * 32 + mf * 16 + a_r) * SAH + kb + a_c;
        ldsm_x4(ah[mf], smem_u32(&Asm[ao]));
        ldsm_x4(al[mf], smem_u32(&Asm[128 * SAH + ao]));
      }
#pragma unroll
      for (int nb = 0; nb < 4; nb++) {
        uint32_t bh[4], bl[4];
        const int bo = (kb + b_row) * SBH + wn * 64 + nb * 16 + b_col;
        ldsm_x4_t(bh, smem_u32(&Bsm[bo]));
        ldsm_x4_t(bl, smem_u32(&Bsm[32 * SBH + bo]));
#pragma unroll
        for (int mf = 0; mf < 2; mf++) {
          mma16816(acc[mf][2 * nb], ah[mf], &bh[0]);
          mma16816(acc[mf][2 * nb + 1], ah[mf], &bh[2]);
          mma16816(acc[mf][2 * nb], ah[mf], &bl[0]);
          mma16816(acc[mf][2 * nb + 1], ah[mf], &bl[2]);
          mma16816(acc[mf][2 * nb], al[mf], &bh[0]);
          mma16816(acc[mf][2 * nb + 1], al[mf], &bh[2]);
        }
      }
    }
  }
#undef CP_CHUNK

#pragma unroll
  for (int mf = 0; mf < 2; mf++)
#pragma unroll
    for (int nf = 0; nf < 8; nf++) {
      const int o = o0 + wm * 32 + mf * 16 + (lane >> 2);
      const int t = t0 + wn * 64 + nf * 8 + ((lane & 3) << 1);
      const size_t off0 = ((size_t)bz * OC + o) * NHW + t;
      const size_t off1 = off0 + (size_t)8 * NHW;
      const float bi0 = bias[o], bi1 = bias[o + 8];
      float y0 = acc[mf][nf][0] + bi0, y1 = acc[mf][nf][1] + bi0;
      float y2 = acc[mf][nf][2] + bi1, y3 = acc[mf][nf][3] + bi1;
      if (EMIT) {
        uint32_t h01 = packbf2(y0, y1), h23 = packbf2(y2, y3);
        uint32_t l01 = packbf2(y0 - bflo_f(h01), y1 - bfhi_f(h01));
        uint32_t l23 = packbf2(y2 - bflo_f(h23), y3 - bfhi_f(h23));
        *(uint32_t*)(Yhi + off0) = h01;
        *(uint32_t*)(Yhi + off1) = h23;
        *(uint32_t*)(Ylo + off0) = l01;
        *(uint32_t*)(Ylo + off1) = l23;
      } else {
        float2 r0 = *(const float2*)(R + off0);
        float2 r1 = *(const float2*)(R + off1);
        *(float2*)(Yf + off0) = make_float2(y0 + r0.x, y1 + r0.y);
        *(float2*)(Yf + off1) = make_float2(y2 + r1.x, y3 + r1.y);
      }
    }
}

// ---------------------------------------------------------------------------
// Flash attention v3: m16 warp tiles, 64-wide key tiles, occupancy 2.
// CTA: (b,h, t-tile 128); 8 warps each own m16 rows. 16 key tiles of 64.
// smem: Q[64][136]x2, K[64][72]x2, V[64][72]x2  = 70 KB -> 2 CTA/SM.
// ---------------------------------------------------------------------------
#define AQH2 136
#define AKH 72
#define SM_SCALE_LOG2 0.1803368801f

__global__ void __launch_bounds__(256, 2) attn_mma_kernel(
    const ushort_t* __restrict__ qkvhi, const ushort_t* __restrict__ qkvlo,
    ushort_t* __restrict__ outhi, ushort_t* __restrict__ outlo) {
  extern __shared__ __align__(16) ushort_t smem[];
  ushort_t* Qh = smem;                  // 64*136
  ushort_t* Ql = Qh + 64 * AQH2;
  ushort_t* Kh = Ql + 64 * AQH2;        // 64*72
  ushort_t* Kl = Kh + 64 * AKH;
  ushort_t* Vh = Kl + 64 * AKH;         // 64*72 (transposed [s][d])
  ushort_t* Vl = Vh + 64 * AKH;

  const int tid = threadIdx.x, lane = tid & 31, warp = tid >> 5;
  const int bh_ = blockIdx.y;
  const int b = bh_ >> 3, h = bh_ & 7;
  const int t0 = blockIdx.x * 128;

  const ushort_t* qhp = qkvhi + ((size_t)b * OC3 + h * HD) * NHW;
  const ushort_t* qlp = qkvlo + ((size_t)b * OC3 + h * HD) * NHW;
  const ushort_t* khp = qhp + (size_t)NC * NHW;
  const ushort_t* klp = qlp + (size_t)NC * NHW;
  const ushort_t* vhp = qhp + (size_t)2 * NC * NHW;
  const ushort_t* vlp = qlp + (size_t)2 * NC * NHW;

  // Load Q [d 64][t 128], both planes
#pragma unroll
  for (int i = 0; i < 8; i++) {
    const int idx = i * 256 + tid;
    const int pl = idx >> 10, u = idx & 1023;
    const int r = u >> 4, c = u & 15;
    ushort_t* dst = (pl ? Ql : Qh) + r * AQH2 + c * 8;
    const ushort_t* src = (pl ? qlp : qhp) + (size_t)r * NHW + t0 + c * 8;
    *(uint4*)dst = *(const uint4*)src;
  }
  __syncthreads();

  const int a_kr = ((lane >> 4) << 3) + (lane & 7);
  const int a_mc = ((lane >> 3) & 1) << 3;
  const int b_g = lane >> 3;
  const int b_row = ((b_g & 1) << 3) + (lane & 7);
  const int b_col = (b_g >> 1) << 3;

  // Hoist both Q planes as A-fragments (m16)
  uint32_t aq[4][4], aql[4][4];
#pragma unroll
  for (int k4 = 0; k4 < 4; k4++) {
    const int ao = (k4 * 16 + a_kr) * AQH2 + warp * 16 + a_mc;
    ldsm_x4_t(aq[k4], smem_u32(&Qh[ao]));
    ldsm_x4_t(aql[k4], smem_u32(&Ql[ao]));
  }

  float o8[8][4] = {};
  float m0 = -1e30f, m1 = -1e30f, l0 = 0.f, l1 = 0.f;

#pragma unroll 1
  for (int s0 = 0; s0 < NHW; s0 += 64) {
    // K tile [d 64][s 64], both planes
#pragma unroll
    for (int i = 0; i < 4; i++) {
      const int idx = i * 256 + tid;
      const int pl = idx >> 9, u = idx & 511;
      const int r = u >> 3, c = u & 7;
      ushort_t* dst = (pl ? Kl : Kh) + r * AKH + c * 8;
      const ushort_t* src = (pl ? klp : khp) + (size_t)r * NHW + s0 + c * 8;
      *(uint4*)dst = *(const uint4*)src;
    }
    // V tile transposed [s 64][d 64], both planes
#pragma unroll
    for (int i = 0; i < 2; i++) {
      const int idx = i * 256 + tid;
      const int pl = idx >> 8, u = idx & 255;
      const int dp = u & 31, sc = u >> 5;  // d-pair, s-chunk of 8
      const ushort_t* src = pl ? vlp : vhp;
      ushort_t* dst = pl ? Vl : Vh;
      uint4 r0 = *(const uint4*)(src + (size_t)(2 * dp) * NHW + s0 + sc * 8);
      uint4 r1 =
          *(const uint4*)(src + (size_t)(2 * dp + 1) * NHW + s0 + sc * 8);
      uint32_t q0[4] = {r0.x, r0.y, r0.z, r0.w};
      uint32_t q1[4] = {r1.x, r1.y, r1.z, r1.w};
#pragma unroll
      for (int j2 = 0; j2 < 4; j2++) {
        uint32_t a = q0[j2], bq = q1[j2];
        uint32_t w0 = (a & 0xffffu) | (bq << 16);
        uint32_t w1 = (a >> 16) | (bq & 0xffff0000u);
        const int s = sc * 8 + 2 * j2;
        *(uint32_t*)&dst[s * AKH + 2 * dp] = w0;
        *(uint32_t*)&dst[(s + 1) * AKH + 2 * dp] = w1;
      }
    }
    __syncthreads();

    // ---- S = Q^T K (m16 x n64, k=64), 3-term split ----
    float sacc[8][4] = {};
#pragma unroll
    for (int k4 = 0; k4 < 4; k4++) {
#pragma unroll
      for (int nb = 0; nb < 4; nb++) {
        uint32_t kbh[4], kbl[4];
        const int bo = (k4 * 16 + b_row) * AKH + nb * 16 + b_col;
        ldsm_x4_t(kbh, smem_u32(&Kh[bo]));
        ldsm_x4_t(kbl, smem_u32(&Kl[bo]));
        mma16816(sacc[2 * nb], aq[k4], &kbh[0]);
        mma16816(sacc[2 * nb + 1], aq[k4], &kbh[2]);
        mma16816(sacc[2 * nb], aq[k4], &kbl[0]);
        mma16816(sacc[2 * nb + 1], aq[k4], &kbl[2]);
        mma16816(sacc[2 * nb], aql[k4], &kbh[0]);
        mma16816(sacc[2 * nb + 1], aql[k4], &kbh[2]);
      }
    }

    // ---- online softmax (base-2) ----
    float mt0 = -1e30f, mt1 = -1e30f;
#pragma unroll
    for (int f = 0; f < 8; f++) {
      sacc[f][0] *= SM_SCALE_LOG2;
      sacc[f][1] *= SM_SCALE_LOG2;
      sacc[f][2] *= SM_SCALE_LOG2;
      sacc[f][3] *= SM_SCALE_LOG2;
      mt0 = fmaxf(mt0, fmaxf(sacc[f][0], sacc[f][1]));
      mt1 = fmaxf(mt1, fmaxf(sacc[f][2], sacc[f][3]));
    }
    mt0 = fmaxf(mt0, __shfl_xor_sync(0xffffffffu, mt0, 1));
    mt0 = fmaxf(mt0, __shfl_xor_sync(0xffffffffu, mt0, 2));
    mt1 = fmaxf(mt1, __shfl_xor_sync(0xffffffffu, mt1, 1));
    mt1 = fmaxf(mt1, __shfl_xor_sync(0xffffffffu, mt1, 2));
    const float mn0 = fmaxf(m0, mt0), mn1 = fmaxf(m1, mt1);
    const float fac0 = ex2f(m0 - mn0), fac1 = ex2f(m1 - mn1);
    m0 = mn0; m1 = mn1;
    float rs0 = 0.f, rs1 = 0.f;
#pragma unroll
    for (int f = 0; f < 8; f++) {
      sacc[f][0] = ex2f(sacc[f][0] - mn0);
      sacc[f][1] = ex2f(sacc[f][1] - mn0);
      sacc[f][2] = ex2f(sacc[f][2] - mn1);
      sacc[f][3] = ex2f(sacc[f][3] - mn1);
      rs0 += sacc[f][0] + sacc[f][1];
      rs1 += sacc[f][2] + sacc[f][3];
    }
    rs0 += __shfl_xor_sync(0xffffffffu, rs0, 1);
    rs0 += __shfl_xor_sync(0xffffffffu, rs0, 2);
    rs1 += __shfl_xor_sync(0xffffffffu, rs1, 1);
    rs1 += __shfl_xor_sync(0xffffffffu, rs1, 2);
    l0 = l0 * fac0 + rs0;
    l1 = l1 * fac1 + rs1;
#pragma unroll
    for (int f = 0; f < 8; f++) {
      o8[f][0] *= fac0; o8[f][1] *= fac0;
      o8[f][2] *= fac1; o8[f][3] *= fac1;
    }

    // ---- pack P (S frags -> A frags), hi/lo ----
    uint32_t Ph[4][4], Pw[4][4];
#pragma unroll
    for (int f = 0; f < 8; f++) {
      const int k8 = f >> 1, sl = (f & 1) << 1;
      uint32_t h01 = packbf2(sacc[f][0], sacc[f][1]);
      uint32_t h23 = packbf2(sacc[f][2], sacc[f][3]);
      Ph[k8][sl] = h01;
      Ph[k8][sl + 1] = h23;
      Pw[k8][sl] = packbf2(sacc[f][0] - bflo_f(h01), sacc[f][1] - bfhi_f(h01));
      Pw[k8][sl + 1] =
          packbf2(sacc[f][2] - bflo_f(h23), sacc[f][3] - bfhi_f(h23));
    }

    // ---- O += P V (m16 x n64, k=64) ----
#pragma unroll
    for (int k8 = 0; k8 < 4; k8++) {
#pragma unroll
      for (int nb = 0; nb < 4; nb++) {
        uint32_t vh[4], vl[4];
        const int vo = (k8 * 16 + b_row) * AKH + nb * 16 + b_col;
        ldsm_x4_t(vh, smem_u32(&Vh[vo]));
        ldsm_x4_t(vl, smem_u32(&Vl[vo]));
        mma16816(o8[2 * nb], Ph[k8], &vh[0]);
        mma16816(o8[2 * nb + 1], Ph[k8], &vh[2]);
        mma16816(o8[2 * nb], Ph[k8], &vl[0]);
        mma16816(o8[2 * nb + 1], Ph[k8], &vl[2]);
        mma16816(o8[2 * nb], Pw[k8], &vh[0]);
        mma16816(o8[2 * nb + 1], Pw[k8], &vh[2]);
      }
    }
    __syncthreads();
  }

  // ---- epilogue: normalize, stage [d 64][t 128] f32 in Q area, emit ----
  float* Ost = (float*)Qh;  // 64 x 132 floats = 33.8KB fits in Qh+Ql
  const float inv0 = 1.f / l0, inv1 = 1.f / l1;
  const int tl = warp * 16 + (lane >> 2);
#pragma unroll
  for (int f = 0; f < 8; f++) {
    const int d = f * 8 + ((lane & 3) << 1);
    Ost[d * 132 + tl] = o8[f][0] * inv0;
    Ost[(d + 1) * 132 + tl] = o8[f][1] * inv0;
    Ost[d * 132 + tl + 8] = o8[f][2] * inv1;
    Ost[(d + 1) * 132 + tl + 8] = o8[f][3] * inv1;
  }
  __syncthreads();
#pragma unroll
  for (int i = 0; i < 4; i++) {
    const int idx = i * 256 + tid;
    const int r = idx >> 4, c = idx & 15;
    const float* src = &Ost[r * 132 + c * 8];
    uint32_t hu[4], lu[4];
#pragma unroll
    for (int j = 0; j < 4; j++) {
      float v0 = src[2 * j], v1 = src[2 * j + 1];
      hu[j] = packbf2(v0, v1);
      lu[j] = packbf2(v0 - bflo_f(hu[j]), v1 - bfhi_f(hu[j]));
    }
    const size_t off = ((size_t)b * NC + h * HD + r) * NHW + t0 + c * 8;
    *(uint4*)(outhi + off) = make_uint4(hu[0], hu[1], hu[2], hu[3]);
    *(uint4*)(outlo + off) = make_uint4(lu[0], lu[1], lu[2], lu[3]);
  }
}

// ---------------------------------------------------------------------------
extern "C" void kernel_launch(void* const* d_in, const int* in_sizes, int n_in,
                              void* d_out, int out_size) {
  const float* x = (const float*)d_in[0];
  const float* gn_gamma = (const float*)d_in[1];
  const float* gn_beta = (const float*)d_in[2];
  const float* qkv_w = (const float*)d_in[3];
  const float* qkv_b = (const float*)d_in[4];
  const float* proj_w = (const float*)d_in[5];
  const float* proj_b = (const float*)d_in[6];
  float* out = (float*)d_out;

  ushort_t *wqh, *wql, *wph, *wpl, *xnh, *xnl, *qh, *qlo, *ath, *atl;
  cudaGetSymbolAddress((void**)&wqh, g_wqhi);
  cudaGetSymbolAddress((void**)&wql, g_wqlo);
  cudaGetSymbolAddress((void**)&wph, g_wphi);
  cudaGetSymbolAddress((void**)&wpl, g_wplo);
  cudaGetSymbolAddress((void**)&xnh, g_xnhi);
  cudaGetSymbolAddress((void**)&xnl, g_xnlo);
  cudaGetSymbolAddress((void**)&qh, g_qkvhi);
  cudaGetSymbolAddress((void**)&qlo, g_qkvlo);
  cudaGetSymbolAddress((void**)&ath, g_atthi);
  cudaGetSymbolAddress((void**)&atl, g_attlo);

  const int ATT_SMEM =
      (2 * 64 * AQH2 + 4 * 64 * AKH) * (int)sizeof(ushort_t);  // 71680 B
  cudaFuncSetAttribute(attn_mma_kernel,
                       cudaFuncAttributeMaxDynamicSharedMemorySize, ATT_SMEM);
  cudaFuncSetAttribute(gemm_bf16_kernel<OC3, true>,
                       cudaFuncAttributeMaxDynamicSharedMemorySize, GEMM_SMEM);
  cudaFuncSetAttribute(gemm_bf16_kernel<NC, false>,
                       cudaFuncAttributeMaxDynamicSharedMemorySize, GEMM_SMEM);

  gn_kernel<<<NB * NG, 256>>>(x, gn_gamma, gn_beta);
  prep_w_kernel<<<(OC3 * NC + NC * NC) / 4 / 256, 256>>>(qkv_w, proj_w);
  gemm_bf16_kernel<OC3, true><<<dim3(8, 12, NB), 256, GEMM_SMEM>>>(
      wqh, wql, qkv_b, xnh, xnl, nullptr, nullptr, qh, qlo);
  attn_mma_kernel<<<dim3(8, NB * NHEADS), 256, ATT_SMEM>>>(qh, qlo, ath, atl);
  gemm_bf16_kernel<NC, false><<<dim3(8, 4, NB), 256, GEMM_SMEM>>>(
      wph, wpl, proj_b, ath, atl, x, out, nullptr, nullptr);
}

// round 15
// speedup vs baseline: 2.5876x; 1.6402x over previous
#include <cuda_runtime.h>
#include <cuda_fp16.h>
#include <math.h>
#include <stdint.h>

#define NB 16
#define NC 512
#define NHW 1024
#define NHEADS 8
#define HD 64
#define NG 32
#define OC3 1536
#define GN_EPS 1e-5f

typedef unsigned short ushort_t;

// Scratch (static device globals — allocation-free per harness rules)
__device__ ushort_t g_wqhi[(size_t)OC3 * NC];
__device__ ushort_t g_wqlo[(size_t)OC3 * NC];
__device__ ushort_t g_wphi[(size_t)NC * NC];
__device__ ushort_t g_wplo[(size_t)NC * NC];
__device__ ushort_t g_xn[(size_t)NB * NC * NHW];      // single fp16 plane
__device__ ushort_t g_qkvhi[(size_t)NB * OC3 * NHW];  // fp16 hi
__device__ ushort_t g_qkvlo[(size_t)NB * OC3 * NHW];  // fp16 lo (Q only read)
__device__ ushort_t g_att[(size_t)NB * NC * NHW];     // single fp16 plane

// ============================ helpers ======================================
__device__ __forceinline__ uint32_t smem_u32(const void* p) {
  uint32_t a;
  asm("{ .reg .u64 t; cvta.to.shared.u64 t, %1; cvt.u32.u64 %0, t; }"
      : "=r"(a) : "l"(p));
  return a;
}
__device__ __forceinline__ float ex2f(float x) {
  float r;
  asm("ex2.approx.ftz.f32 %0, %1;" : "=f"(r) : "f"(x));
  return r;
}
// pack two floats to fp16x2 (v0 -> low half)
__device__ __forceinline__ uint32_t packh2(float v0, float v1) {
  __half2 h = __floats2half2_rn(v0, v1);
  return *(uint32_t*)&h;
}
// split pair into hi/lo fp16 planes
__device__ __forceinline__ void splith2(float v0, float v1, uint32_t& h,
                                        uint32_t& l) {
  __half a = __float2half_rn(v0), b = __float2half_rn(v1);
  float r0 = v0 - __half2float(a), r1 = v1 - __half2float(b);
  __half la = __float2half_rn(r0), lb = __float2half_rn(r1);
  h = (uint32_t)__half_as_ushort(a) | ((uint32_t)__half_as_ushort(b) << 16);
  l = (uint32_t)__half_as_ushort(la) | ((uint32_t)__half_as_ushort(lb) << 16);
}
__device__ __forceinline__ void ldsm_x4(uint32_t* r, uint32_t addr) {
  asm volatile("ldmatrix.sync.aligned.m8n8.x4.shared.b16 {%0,%1,%2,%3}, [%4];"
               : "=r"(r[0]), "=r"(r[1]), "=r"(r[2]), "=r"(r[3]) : "r"(addr));
}
__device__ __forceinline__ void ldsm_x4_t(uint32_t* r, uint32_t addr) {
  asm volatile(
      "ldmatrix.sync.aligned.m8n8.x4.trans.shared.b16 {%0,%1,%2,%3}, [%4];"
      : "=r"(r[0]), "=r"(r[1]), "=r"(r[2]), "=r"(r[3]) : "r"(addr));
}
__device__ __forceinline__ void mma16816(float* d, const uint32_t* a,
                                         const uint32_t* b) {
  asm volatile(
      "mma.sync.aligned.m16n8k16.row.col.f32.f16.f16.f32 "
      "{%0,%1,%2,%3}, {%4,%5,%6,%7}, {%8,%9}, {%0,%1,%2,%3};"
      : "+f"(d[0]), "+f"(d[1]), "+f"(d[2]), "+f"(d[3])
      : "r"(a[0]), "r"(a[1]), "r"(a[2]), "r"(a[3]), "r"(b[0]), "r"(b[1]));
}
__device__ __forceinline__ void cp_async16(uint32_t dst, const void* src) {
  asm volatile("cp.async.cg.shared.global [%0], [%1], 16;" :: "r"(dst),
               "l"(src));
}
#define CP_COMMIT() asm volatile("cp.async.commit_group;" ::: "memory")
#define CP_WAIT(n) asm volatile("cp.async.wait_group %0;" :: "n"(n) : "memory")

// ---------------------------------------------------------------------------
// Weight prep: fp32 -> hi/lo fp16 planes (once per launch)
// ---------------------------------------------------------------------------
__global__ void __launch_bounds__(256) prep_w_kernel(
    const float* __restrict__ qkv_w, const float* __restrict__ proj_w) {
  const int idx = blockIdx.x * 256 + threadIdx.x;
  const int nq = OC3 * NC / 4;
  const float* src;
  ushort_t *dh, *dl;
  int off;
  if (idx < nq) {
    src = qkv_w; dh = g_wqhi; dl = g_wqlo; off = idx * 4;
  } else {
    src = proj_w; dh = g_wphi; dl = g_wplo; off = (idx - nq) * 4;
  }
  float4 v = *(const float4*)(src + off);
  uint32_t h01, l01, h23, l23;
  splith2(v.x, v.y, h01, l01);
  splith2(v.z, v.w, h23, l23);
  *(uint2*)(dh + off) = make_uint2(h01, h23);
  *(uint2*)(dl + off) = make_uint2(l01, l23);
}

// ---------------------------------------------------------------------------
// GroupNorm -> single fp16 plane
// ---------------------------------------------------------------------------
__global__ void __launch_bounds__(256) gn_kernel(
    const float* __restrict__ x, const float* __restrict__ gamma,
    const float* __restrict__ beta) {
  const int bg = blockIdx.x;
  const int g = bg & (NG - 1);
  const size_t base = (size_t)bg * (NC / NG) * NHW;
  const float* px = x + base;
  ushort_t* po = g_xn + base;
  const int tid = threadIdx.x;

  float s = 0.f, q = 0.f;
#pragma unroll
  for (int k = 0; k < 16; k++) {
    float4 v = *(const float4*)(px + (size_t)(tid + k * 256) * 4);
    s += v.x + v.y + v.z + v.w;
    q += v.x * v.x + v.y * v.y + v.z * v.z + v.w * v.w;
  }
#pragma unroll
  for (int off = 16; off; off >>= 1) {
    s += __shfl_xor_sync(0xffffffffu, s, off);
    q += __shfl_xor_sync(0xffffffffu, q, off);
  }
  __shared__ float ss[8], sq[8];
  __shared__ float s_mean, s_inv;
  const int w = tid >> 5;
  if ((tid & 31) == 0) { ss[w] = s; sq[w] = q; }
  __syncthreads();
  if (tid == 0) {
    float ts = 0.f, tq = 0.f;
#pragma unroll
    for (int i = 0; i < 8; i++) { ts += ss[i]; tq += sq[i]; }
    float mean = ts * (1.f / 16384.f);
    float var = tq * (1.f / 16384.f) - mean * mean;
    s_mean = mean;
    s_inv = rsqrtf(var + GN_EPS);
  }
  __syncthreads();
  const float mean = s_mean, inv = s_inv;
#pragma unroll
  for (int k = 0; k < 16; k++) {
    size_t off = (size_t)(tid + k * 256) * 4;
    int c = g * 16 + (int)(off >> 10);
    float ga = gamma[c], be = beta[c];
    float4 v = *(const float4*)(px + off);
    v.x = (v.x - mean) * inv * ga + be;
    v.y = (v.y - mean) * inv * ga + be;
    v.z = (v.z - mean) * inv * ga + be;
    v.w = (v.w - mean) * inv * ga + be;
    *(uint2*)(po + off) = make_uint2(packh2(v.x, v.y), packh2(v.z, v.w));
  }
}

// ---------------------------------------------------------------------------
// fp16 GEMM, 2-term split (W hi/lo, X single), cp.async double-buffered.
// Tile 128(o) x 128(t), K-chunk 32; 8 warps = 4m x 2n; warp 32x64.
// EMIT: write hi/lo fp16 planes. Else fp32 + residual.
// ---------------------------------------------------------------------------
#define SAH 40
#define SBH 136
#define A_ELE (2 * 128 * SAH)
#define B_ELE (32 * SBH)
#define BUF_ELE (A_ELE + B_ELE)
#define GEMM_SMEM (2 * BUF_ELE * (int)sizeof(ushort_t))
#define NCH (NC / 32)

template <int OC, bool EMIT>
__global__ void __launch_bounds__(256, 2) gemm_fp16_kernel(
    const ushort_t* __restrict__ Ahi, const ushort_t* __restrict__ Alo,
    const float* __restrict__ bias, const ushort_t* __restrict__ B,
    const float* __restrict__ R, float* __restrict__ Yf,
    ushort_t* __restrict__ Yhi, ushort_t* __restrict__ Ylo) {
  extern __shared__ __align__(16) ushort_t smem[];

  const int tid = threadIdx.x, lane = tid & 31, wid = tid >> 5;
  const int wm = wid >> 1, wn = wid & 1;
  const int bz = blockIdx.z;
  const int o0 = blockIdx.y * 128;
  const int t0 = blockIdx.x * 128;
  const size_t bb = (size_t)bz * NC * NHW;

  const int a_r = lane & 15, a_c = (lane >> 4) << 3;
  const int b_g = lane >> 3;
  const int b_row = ((b_g & 1) << 3) + (lane & 7);
  const int b_col = (b_g >> 1) << 3;

  float acc[2][8][4] = {};

#define CP_CHUNK(kc, buf)                                                    \
  {                                                                          \
    ushort_t* Asm = smem + (buf)*BUF_ELE;                                    \
    ushort_t* Bsm = Asm + A_ELE;                                             \
    _Pragma("unroll") for (int i = 0; i < 4; i++) {                          \
      const int idx = i * 256 + tid;                                         \
      const int pl = idx >> 9, r = (idx >> 2) & 127, cc = idx & 3;           \
      cp_async16(smem_u32(&Asm[pl * 128 * SAH + r * SAH + cc * 8]),          \
                 (pl ? Alo : Ahi) + (size_t)(o0 + r) * NC + (kc) + cc * 8);  \
    }                                                                        \
    _Pragma("unroll") for (int i = 0; i < 2; i++) {                          \
      const int idx = i * 256 + tid;                                         \
      const int r = idx >> 4, cc = idx & 15;                                 \
      cp_async16(smem_u32(&Bsm[r * SBH + cc * 8]),                           \
                 B + bb + (size_t)((kc) + r) * NHW + t0 + cc * 8);           \
    }                                                                        \
  }

  CP_CHUNK(0, 0);
  CP_COMMIT();

#pragma unroll 1
  for (int chunk = 0; chunk < NCH; chunk++) {
    const int cur = chunk & 1;
    __syncthreads();
    if (chunk < NCH - 1) {
      CP_CHUNK((chunk + 1) * 32, cur ^ 1);
      CP_COMMIT();
      CP_WAIT(1);
    } else {
      CP_WAIT(0);
    }
    __syncthreads();

    const ushort_t* Asm = smem + cur * BUF_ELE;
    const ushort_t* Bsm = Asm + A_ELE;
#pragma unroll
    for (int ks = 0; ks < 2; ks++) {
      const int kb = ks * 16;
      uint32_t ah[2][4], al[2][4];
#pragma unroll
      for (int mf = 0; mf < 2; mf++) {
        const int ao = (wm * 32 + mf * 16 + a_r) * SAH + kb + a_c;
        ldsm_x4(ah[mf], smem_u32(&Asm[ao]));
        ldsm_x4(al[mf], smem_u32(&Asm[128 * SAH + ao]));
      }
#pragma unroll
      for (int nb = 0; nb < 4; nb++) {
        uint32_t bh[4];
        const int bo = (kb + b_row) * SBH + wn * 64 + nb * 16 + b_col;
        ldsm_x4_t(bh, smem_u32(&Bsm[bo]));
#pragma unroll
        for (int mf = 0; mf < 2; mf++) {
          mma16816(acc[mf][2 * nb], ah[mf], &bh[0]);
          mma16816(acc[mf][2 * nb + 1], ah[mf], &bh[2]);
          mma16816(acc[mf][2 * nb], al[mf], &bh[0]);
          mma16816(acc[mf][2 * nb + 1], al[mf], &bh[2]);
        }
      }
    }
  }
#undef CP_CHUNK

#pragma unroll
  for (int mf = 0; mf < 2; mf++)
#pragma unroll
    for (int nf = 0; nf < 8; nf++) {
      const int o = o0 + wm * 32 + mf * 16 + (lane >> 2);
      const int t = t0 + wn * 64 + nf * 8 + ((lane & 3) << 1);
      const size_t off0 = ((size_t)bz * OC + o) * NHW + t;
      const size_t off1 = off0 + (size_t)8 * NHW;
      const float bi0 = bias[o], bi1 = bias[o + 8];
      float y0 = acc[mf][nf][0] + bi0, y1 = acc[mf][nf][1] + bi0;
      float y2 = acc[mf][nf][2] + bi1, y3 = acc[mf][nf][3] + bi1;
      if (EMIT) {
        uint32_t h01, l01, h23, l23;
        splith2(y0, y1, h01, l01);
        splith2(y2, y3, h23, l23);
        *(uint32_t*)(Yhi + off0) = h01;
        *(uint32_t*)(Yhi + off1) = h23;
        *(uint32_t*)(Ylo + off0) = l01;
        *(uint32_t*)(Ylo + off1) = l23;
      } else {
        float2 r0 = *(const float2*)(R + off0);
        float2 r1 = *(const float2*)(R + off1);
        *(float2*)(Yf + off0) = make_float2(y0 + r0.x, y1 + r0.y);
        *(float2*)(Yf + off1) = make_float2(y2 + r1.x, y3 + r1.y);
      }
    }
}

// ---------------------------------------------------------------------------
// Flash attention: m16 warp tiles, 64-wide key tiles, occupancy 2.
// S = (Qh+Ql)^T K (2 terms, K single fp16); PV = P_fp16 * V (1 term).
// smem: Q[64][136]x2, K[64][72], V[64][72] (transposed) = 53 KB.
// ---------------------------------------------------------------------------
#define AQH2 136
#define AKH 72
#define SM_SCALE_LOG2 0.1803368801f

__global__ void __launch_bounds__(256, 2) attn_mma_kernel(
    const ushort_t* __restrict__ qkvhi, const ushort_t* __restrict__ qkvlo,
    ushort_t* __restrict__ outp) {
  extern __shared__ __align__(16) ushort_t smem[];
  ushort_t* Qh = smem;                  // 64*136
  ushort_t* Ql = Qh + 64 * AQH2;
  ushort_t* Ks = Ql + 64 * AQH2;        // 64*72
  ushort_t* Vs = Ks + 64 * AKH;         // 64*72 (transposed [s][d])

  const int tid = threadIdx.x, lane = tid & 31, warp = tid >> 5;
  const int bh_ = blockIdx.y;
  const int b = bh_ >> 3, h = bh_ & 7;
  const int t0 = blockIdx.x * 128;

  const ushort_t* qhp = qkvhi + ((size_t)b * OC3 + h * HD) * NHW;
  const ushort_t* qlp = qkvlo + ((size_t)b * OC3 + h * HD) * NHW;
  const ushort_t* khp = qhp + (size_t)NC * NHW;
  const ushort_t* vhp = qhp + (size_t)2 * NC * NHW;

  // Load Q [d 64][t 128], both planes
#pragma unroll
  for (int i = 0; i < 8; i++) {
    const int idx = i * 256 + tid;
    const int pl = idx >> 10, u = idx & 1023;
    const int r = u >> 4, c = u & 15;
    ushort_t* dst = (pl ? Ql : Qh) + r * AQH2 + c * 8;
    const ushort_t* src = (pl ? qlp : qhp) + (size_t)r * NHW + t0 + c * 8;
    *(uint4*)dst = *(const uint4*)src;
  }
  __syncthreads();

  const int a_kr = ((lane >> 4) << 3) + (lane & 7);
  const int a_mc = ((lane >> 3) & 1) << 3;
  const int b_g = lane >> 3;
  const int b_row = ((b_g & 1) << 3) + (lane & 7);
  const int b_col = (b_g >> 1) << 3;

  // Hoist both Q planes as A-fragments (m16)
  uint32_t aq[4][4], aql[4][4];
#pragma unroll
  for (int k4 = 0; k4 < 4; k4++) {
    const int ao = (k4 * 16 + a_kr) * AQH2 + warp * 16 + a_mc;
    ldsm_x4_t(aq[k4], smem_u32(&Qh[ao]));
    ldsm_x4_t(aql[k4], smem_u32(&Ql[ao]));
  }

  float o8[8][4] = {};
  float m0 = -1e30f, m1 = -1e30f, l0 = 0.f, l1 = 0.f;

#pragma unroll 1
  for (int s0 = 0; s0 < NHW; s0 += 64) {
    // K tile [d 64][s 64] single plane
#pragma unroll
    for (int i = 0; i < 2; i++) {
      const int idx = i * 256 + tid;
      const int r = idx >> 3, c = idx & 7;
      *(uint4*)(Ks + r * AKH + c * 8) =
          *(const uint4*)(khp + (size_t)r * NHW + s0 + c * 8);
    }
    // V tile transposed [s 64][d 64] single plane
    {
      const int dp = tid & 31, sc = tid >> 5;  // d-pair, s-chunk of 8
      uint4 r0 = *(const uint4*)(vhp + (size_t)(2 * dp) * NHW + s0 + sc * 8);
      uint4 r1 =
          *(const uint4*)(vhp + (size_t)(2 * dp + 1) * NHW + s0 + sc * 8);
      uint32_t q0[4] = {r0.x, r0.y, r0.z, r0.w};
      uint32_t q1[4] = {r1.x, r1.y, r1.z, r1.w};
#pragma unroll
      for (int j2 = 0; j2 < 4; j2++) {
        uint32_t a = q0[j2], bq = q1[j2];
        uint32_t w0 = (a & 0xffffu) | (bq << 16);
        uint32_t w1 = (a >> 16) | (bq & 0xffff0000u);
        const int s = sc * 8 + 2 * j2;
        *(uint32_t*)&Vs[s * AKH + 2 * dp] = w0;
        *(uint32_t*)&Vs[(s + 1) * AKH + 2 * dp] = w1;
      }
    }
    __syncthreads();

    // ---- S = Q^T K (m16 x n64, k=64), 2-term split-Q ----
    float sacc[8][4] = {};
#pragma unroll
    for (int k4 = 0; k4 < 4; k4++) {
#pragma unroll
      for (int nb = 0; nb < 4; nb++) {
        uint32_t kb[4];
        const int bo = (k4 * 16 + b_row) * AKH + nb * 16 + b_col;
        ldsm_x4_t(kb, smem_u32(&Ks[bo]));
        mma16816(sacc[2 * nb], aq[k4], &kb[0]);
        mma16816(sacc[2 * nb + 1], aq[k4], &kb[2]);
        mma16816(sacc[2 * nb], aql[k4], &kb[0]);
        mma16816(sacc[2 * nb + 1], aql[k4], &kb[2]);
      }
    }

    // ---- online softmax (base-2) ----
    float mt0 = -1e30f, mt1 = -1e30f;
#pragma unroll
    for (int f = 0; f < 8; f++) {
      sacc[f][0] *= SM_SCALE_LOG2;
      sacc[f][1] *= SM_SCALE_LOG2;
      sacc[f][2] *= SM_SCALE_LOG2;
      sacc[f][3] *= SM_SCALE_LOG2;
      mt0 = fmaxf(mt0, fmaxf(sacc[f][0], sacc[f][1]));
      mt1 = fmaxf(mt1, fmaxf(sacc[f][2], sacc[f][3]));
    }
    mt0 = fmaxf(mt0, __shfl_xor_sync(0xffffffffu, mt0, 1));
    mt0 = fmaxf(mt0, __shfl_xor_sync(0xffffffffu, mt0, 2));
    mt1 = fmaxf(mt1, __shfl_xor_sync(0xffffffffu, mt1, 1));
    mt1 = fmaxf(mt1, __shfl_xor_sync(0xffffffffu, mt1, 2));
    const float mn0 = fmaxf(m0, mt0), mn1 = fmaxf(m1, mt1);
    const float fac0 = ex2f(m0 - mn0), fac1 = ex2f(m1 - mn1);
    m0 = mn0; m1 = mn1;
    float rs0 = 0.f, rs1 = 0.f;
#pragma unroll
    for (int f = 0; f < 8; f++) {
      sacc[f][0] = ex2f(sacc[f][0] - mn0);
      sacc[f][1] = ex2f(sacc[f][1] - mn0);
      sacc[f][2] = ex2f(sacc[f][2] - mn1);
      sacc[f][3] = ex2f(sacc[f][3] - mn1);
      rs0 += sacc[f][0] + sacc[f][1];
      rs1 += sacc[f][2] + sacc[f][3];
    }
    rs0 += __shfl_xor_sync(0xffffffffu, rs0, 1);
    rs0 += __shfl_xor_sync(0xffffffffu, rs0, 2);
    rs1 += __shfl_xor_sync(0xffffffffu, rs1, 1);
    rs1 += __shfl_xor_sync(0xffffffffu, rs1, 2);
    l0 = l0 * fac0 + rs0;
    l1 = l1 * fac1 + rs1;
#pragma unroll
    for (int f = 0; f < 8; f++) {
      o8[f][0] *= fac0; o8[f][1] *= fac0;
      o8[f][2] *= fac1; o8[f][3] *= fac1;
    }

    // ---- pack P (single fp16, S frags -> A frags) ----
    uint32_t Ph[4][4];
#pragma unroll
    for (int f = 0; f < 8; f++) {
      const int k8 = f >> 1, sl = (f & 1) << 1;
      Ph[k8][sl] = packh2(sacc[f][0], sacc[f][1]);
      Ph[k8][sl + 1] = packh2(sacc[f][2], sacc[f][3]);
    }

    // ---- O += P V (m16 x n64, k=64), 1 term ----
#pragma unroll
    for (int k8 = 0; k8 < 4; k8++) {
#pragma unroll
      for (int nb = 0; nb < 4; nb++) {
        uint32_t vv[4];
        const int vo = (k8 * 16 + b_row) * AKH + nb * 16 + b_col;
        ldsm_x4_t(vv, smem_u32(&Vs[vo]));
        mma16816(o8[2 * nb], Ph[k8], &vv[0]);
        mma16816(o8[2 * nb + 1], Ph[k8], &vv[2]);
      }
    }
    __syncthreads();
  }

  // ---- epilogue: normalize, stage [d 64][t 128] f32 in Q area, emit ----
  float* Ost = (float*)Qh;  // 64 x 132 floats fits in Qh+Ql
  const float inv0 = 1.f / l0, inv1 = 1.f / l1;
  const int tl = warp * 16 + (lane >> 2);
#pragma unroll
  for (int f = 0; f < 8; f++) {
    const int d = f * 8 + ((lane & 3) << 1);
    Ost[d * 132 + tl] = o8[f][0] * inv0;
    Ost[(d + 1) * 132 + tl] = o8[f][1] * inv0;
    Ost[d * 132 + tl + 8] = o8[f][2] * inv1;
    Ost[(d + 1) * 132 + tl + 8] = o8[f][3] * inv1;
  }
  __syncthreads();
#pragma unroll
  for (int i = 0; i < 4; i++) {
    const int idx = i * 256 + tid;
    const int r = idx >> 4, c = idx & 15;
    const float* src = &Ost[r * 132 + c * 8];
    uint32_t hu[4];
#pragma unroll
    for (int j = 0; j < 4; j++) hu[j] = packh2(src[2 * j], src[2 * j + 1]);
    const size_t off = ((size_t)b * NC + h * HD + r) * NHW + t0 + c * 8;
    *(uint4*)(outp + off) = make_uint4(hu[0], hu[1], hu[2], hu[3]);
  }
}

// ---------------------------------------------------------------------------
extern "C" void kernel_launch(void* const* d_in, const int* in_sizes, int n_in,
                              void* d_out, int out_size) {
  const float* x = (const float*)d_in[0];
  const float* gn_gamma = (const float*)d_in[1];
  const float* gn_beta = (const float*)d_in[2];
  const float* qkv_w = (const float*)d_in[3];
  const float* qkv_b = (const float*)d_in[4];
  const float* proj_w = (const float*)d_in[5];
  const float* proj_b = (const float*)d_in[6];
  float* out = (float*)d_out;

  ushort_t *wqh, *wql, *wph, *wpl, *xn, *qh, *qlo, *att;
  cudaGetSymbolAddress((void**)&wqh, g_wqhi);
  cudaGetSymbolAddress((void**)&wql, g_wqlo);
  cudaGetSymbolAddress((void**)&wph, g_wphi);
  cudaGetSymbolAddress((void**)&wpl, g_wplo);
  cudaGetSymbolAddress((void**)&xn, g_xn);
  cudaGetSymbolAddress((void**)&qh, g_qkvhi);
  cudaGetSymbolAddress((void**)&qlo, g_qkvlo);
  cudaGetSymbolAddress((void**)&att, g_att);

  const int ATT_SMEM =
      (2 * 64 * AQH2 + 2 * 64 * AKH) * (int)sizeof(ushort_t);  // 53248 B
  cudaFuncSetAttribute(attn_mma_kernel,
                       cudaFuncAttributeMaxDynamicSharedMemorySize, ATT_SMEM);
  cudaFuncSetAttribute(gemm_fp16_kernel<OC3, true>,
                       cudaFuncAttributeMaxDynamicSharedMemorySize, GEMM_SMEM);
  cudaFuncSetAttribute(gemm_fp16_kernel<NC, false>,
                       cudaFuncAttributeMaxDynamicSharedMemorySize, GEMM_SMEM);

  gn_kernel<<<NB * NG, 256>>>(x, gn_gamma, gn_beta);
  prep_w_kernel<<<(OC3 * NC + NC * NC) / 4 / 256, 256>>>(qkv_w, proj_w);
  gemm_fp16_kernel<OC3, true><<<dim3(8, 12, NB), 256, GEMM_SMEM>>>(
      wqh, wql, qkv_b, xn, nullptr, nullptr, qh, qlo);
  attn_mma_kernel<<<dim3(8, NB * NHEADS), 256, ATT_SMEM>>>(qh, qlo, att);
  gemm_fp16_kernel<NC, false><<<dim3(8, 4, NB), 256, GEMM_SMEM>>>(
      wph, wpl, proj_b, att, x, out, nullptr, nullptr);
}

// round 16
// speedup vs baseline: 3.6645x; 1.4161x over previous
#include <cuda_runtime.h>
#include <cuda_fp16.h>
#include <math.h>
#include <stdint.h>

#define NB 16
#define NC 512
#define NHW 1024
#define NHEADS 8
#define HD 64
#define NG 32
#define OC3 1536
#define GN_EPS 1e-5f

typedef unsigned short ushort_t;

// Scratch (static device globals — allocation-free per harness rules)
__device__ ushort_t g_wq[(size_t)OC3 * NC];       // single fp16
__device__ ushort_t g_wp[(size_t)NC * NC];        // single fp16
__device__ ushort_t g_xn[(size_t)NB * NC * NHW];  // single fp16
__device__ ushort_t g_qkv[(size_t)NB * OC3 * NHW];
__device__ ushort_t g_att[(size_t)NB * NC * NHW];

// ============================ helpers ======================================
__device__ __forceinline__ uint32_t smem_u32(const void* p) {
  uint32_t a;
  asm("{ .reg .u64 t; cvta.to.shared.u64 t, %1; cvt.u32.u64 %0, t; }"
      : "=r"(a) : "l"(p));
  return a;
}
__device__ __forceinline__ float ex2f(float x) {
  float r;
  asm("ex2.approx.ftz.f32 %0, %1;" : "=f"(r) : "f"(x));
  return r;
}
__device__ __forceinline__ uint32_t packh2(float v0, float v1) {
  __half2 h = __floats2half2_rn(v0, v1);
  return *(uint32_t*)&h;
}
__device__ __forceinline__ void ldsm_x4(uint32_t* r, uint32_t addr) {
  asm volatile("ldmatrix.sync.aligned.m8n8.x4.shared.b16 {%0,%1,%2,%3}, [%4];"
               : "=r"(r[0]), "=r"(r[1]), "=r"(r[2]), "=r"(r[3]) : "r"(addr));
}
__device__ __forceinline__ void ldsm_x4_t(uint32_t* r, uint32_t addr) {
  asm volatile(
      "ldmatrix.sync.aligned.m8n8.x4.trans.shared.b16 {%0,%1,%2,%3}, [%4];"
      : "=r"(r[0]), "=r"(r[1]), "=r"(r[2]), "=r"(r[3]) : "r"(addr));
}
__device__ __forceinline__ void mma16816(float* d, const uint32_t* a,
                                         const uint32_t* b) {
  asm volatile(
      "mma.sync.aligned.m16n8k16.row.col.f32.f16.f16.f32 "
      "{%0,%1,%2,%3}, {%4,%5,%6,%7}, {%8,%9}, {%0,%1,%2,%3};"
      : "+f"(d[0]), "+f"(d[1]), "+f"(d[2]), "+f"(d[3])
      : "r"(a[0]), "r"(a[1]), "r"(a[2]), "r"(a[3]), "r"(b[0]), "r"(b[1]));
}
__device__ __forceinline__ void cp_async16(uint32_t dst, const void* src) {
  asm volatile("cp.async.cg.shared.global [%0], [%1], 16;" :: "r"(dst),
               "l"(src));
}
#define CP_COMMIT() asm volatile("cp.async.commit_group;" ::: "memory")
#define CP_WAIT(n) asm volatile("cp.async.wait_group %0;" :: "n"(n) : "memory")

// ---------------------------------------------------------------------------
// Weight prep: fp32 -> single fp16
// ---------------------------------------------------------------------------
__global__ void __launch_bounds__(256) prep_w_kernel(
    const float* __restrict__ qkv_w, const float* __restrict__ proj_w) {
  const int idx = blockIdx.x * 256 + threadIdx.x;
  const int nq = OC3 * NC / 4;
  const float* src;
  ushort_t* dh;
  int off;
  if (idx < nq) {
    src = qkv_w; dh = g_wq; off = idx * 4;
  } else {
    src = proj_w; dh = g_wp; off = (idx - nq) * 4;
  }
  float4 v = *(const float4*)(src + off);
  *(uint2*)(dh + off) = make_uint2(packh2(v.x, v.y), packh2(v.z, v.w));
}

// ---------------------------------------------------------------------------
// GroupNorm -> single fp16 plane
// ---------------------------------------------------------------------------
__global__ void __launch_bounds__(256) gn_kernel(
    const float* __restrict__ x, const float* __restrict__ gamma,
    const float* __restrict__ beta) {
  const int bg = blockIdx.x;
  const int g = bg & (NG - 1);
  const size_t base = (size_t)bg * (NC / NG) * NHW;
  const float* px = x + base;
  ushort_t* po = g_xn + base;
  const int tid = threadIdx.x;

  float s = 0.f, q = 0.f;
#pragma unroll
  for (int k = 0; k < 16; k++) {
    float4 v = *(const float4*)(px + (size_t)(tid + k * 256) * 4);
    s += v.x + v.y + v.z + v.w;
    q += v.x * v.x + v.y * v.y + v.z * v.z + v.w * v.w;
  }
#pragma unroll
  for (int off = 16; off; off >>= 1) {
    s += __shfl_xor_sync(0xffffffffu, s, off);
    q += __shfl_xor_sync(0xffffffffu, q, off);
  }
  __shared__ float ss[8], sq[8];
  __shared__ float s_mean, s_inv;
  const int w = tid >> 5;
  if ((tid & 31) == 0) { ss[w] = s; sq[w] = q; }
  __syncthreads();
  if (tid == 0) {
    float ts = 0.f, tq = 0.f;
#pragma unroll
    for (int i = 0; i < 8; i++) { ts += ss[i]; tq += sq[i]; }
    float mean = ts * (1.f / 16384.f);
    float var = tq * (1.f / 16384.f) - mean * mean;
    s_mean = mean;
    s_inv = rsqrtf(var + GN_EPS);
  }
  __syncthreads();
  const float mean = s_mean, inv = s_inv;
#pragma unroll
  for (int k = 0; k < 16; k++) {
    size_t off = (size_t)(tid + k * 256) * 4;
    int c = g * 16 + (int)(off >> 10);
    float ga = gamma[c], be = beta[c];
    float4 v = *(const float4*)(px + off);
    v.x = (v.x - mean) * inv * ga + be;
    v.y = (v.y - mean) * inv * ga + be;
    v.z = (v.z - mean) * inv * ga + be;
    v.w = (v.w - mean) * inv * ga + be;
    *(uint2*)(po + off) = make_uint2(packh2(v.x, v.y), packh2(v.z, v.w));
  }
}

// ---------------------------------------------------------------------------
// fp16 GEMM, single-term, cp.async double-buffered.
// Tile 128(o) x 128(t), K-chunk 32; 8 warps = 4m x 2n; warp 32x64.
// ---------------------------------------------------------------------------
#define SAH 40
#define SBH 136
#define A_ELE (128 * SAH)
#define B_ELE (32 * SBH)
#define BUF_ELE (A_ELE + B_ELE)
#define GEMM_SMEM (2 * BUF_ELE * (int)sizeof(ushort_t))
#define NCH (NC / 32)

template <int OC, bool EMIT>
__global__ void __launch_bounds__(256, 2) gemm_fp16_kernel(
    const ushort_t* __restrict__ A, const float* __restrict__ bias,
    const ushort_t* __restrict__ B, const float* __restrict__ R,
    float* __restrict__ Yf, ushort_t* __restrict__ Yh) {
  extern __shared__ __align__(16) ushort_t smem[];

  const int tid = threadIdx.x, lane = tid & 31, wid = tid >> 5;
  const int wm = wid >> 1, wn = wid & 1;
  const int bz = blockIdx.z;
  const int o0 = blockIdx.y * 128;
  const int t0 = blockIdx.x * 128;
  const size_t bb = (size_t)bz * NC * NHW;

  const int a_r = lane & 15, a_c = (lane >> 4) << 3;
  const int b_g = lane >> 3;
  const int b_row = ((b_g & 1) << 3) + (lane & 7);
  const int b_col = (b_g >> 1) << 3;

  float acc[2][8][4] = {};

#define CP_CHUNK(kc, buf)                                                    \
  {                                                                          \
    ushort_t* Asm = smem + (buf)*BUF_ELE;                                    \
    ushort_t* Bsm = Asm + A_ELE;                                             \
    _Pragma("unroll") for (int i = 0; i < 2; i++) {                          \
      const int idx = i * 256 + tid;                                         \
      const int r = idx >> 2, cc = idx & 3;                                  \
      cp_async16(smem_u32(&Asm[r * SAH + cc * 8]),                           \
                 A + (size_t)(o0 + r) * NC + (kc) + cc * 8);                 \
    }                                                                        \
    _Pragma("unroll") for (int i = 0; i < 2; i++) {                          \
      const int idx = i * 256 + tid;                                         \
      const int r = idx >> 4, cc = idx & 15;                                 \
      cp_async16(smem_u32(&Bsm[r * SBH + cc * 8]),                           \
                 B + bb + (size_t)((kc) + r) * NHW + t0 + cc * 8);           \
    }                                                                        \
  }

  CP_CHUNK(0, 0);
  CP_COMMIT();

#pragma unroll 1
  for (int chunk = 0; chunk < NCH; chunk++) {
    const int cur = chunk & 1;
    __syncthreads();
    if (chunk < NCH - 1) {
      CP_CHUNK((chunk + 1) * 32, cur ^ 1);
      CP_COMMIT();
      CP_WAIT(1);
    } else {
      CP_WAIT(0);
    }
    __syncthreads();

    const ushort_t* Asm = smem + cur * BUF_ELE;
    const ushort_t* Bsm = Asm + A_ELE;
#pragma unroll
    for (int ks = 0; ks < 2; ks++) {
      const int kb = ks * 16;
      uint32_t ah[2][4];
#pragma unroll
      for (int mf = 0; mf < 2; mf++) {
        const int ao = (wm * 32 + mf * 16 + a_r) * SAH + kb + a_c;
        ldsm_x4(ah[mf], smem_u32(&Asm[ao]));
      }
#pragma unroll
      for (int nb = 0; nb < 4; nb++) {
        uint32_t bh[4];
        const int bo = (kb + b_row) * SBH + wn * 64 + nb * 16 + b_col;
        ldsm_x4_t(bh, smem_u32(&Bsm[bo]));
#pragma unroll
        for (int mf = 0; mf < 2; mf++) {
          mma16816(acc[mf][2 * nb], ah[mf], &bh[0]);
          mma16816(acc[mf][2 * nb + 1], ah[mf], &bh[2]);
        }
      }
    }
  }
#undef CP_CHUNK

#pragma unroll
  for (int mf = 0; mf < 2; mf++)
#pragma unroll
    for (int nf = 0; nf < 8; nf++) {
      const int o = o0 + wm * 32 + mf * 16 + (lane >> 2);
      const int t = t0 + wn * 64 + nf * 8 + ((lane & 3) << 1);
      const size_t off0 = ((size_t)bz * OC + o) * NHW + t;
      const size_t off1 = off0 + (size_t)8 * NHW;
      const float bi0 = bias[o], bi1 = bias[o + 8];
      float y0 = acc[mf][nf][0] + bi0, y1 = acc[mf][nf][1] + bi0;
      float y2 = acc[mf][nf][2] + bi1, y3 = acc[mf][nf][3] + bi1;
      if (EMIT) {
        *(uint32_t*)(Yh + off0) = packh2(y0, y1);
        *(uint32_t*)(Yh + off1) = packh2(y2, y3);
      } else {
        float2 r0 = *(const float2*)(R + off0);
        float2 r1 = *(const float2*)(R + off1);
        *(float2*)(Yf + off0) = make_float2(y0 + r0.x, y1 + r0.y);
        *(float2*)(Yf + off1) = make_float2(y2 + r1.x, y3 + r1.y);
      }
    }
}

// ---------------------------------------------------------------------------
// Flash attention: m16 warp tiles, 64-wide key tiles, occupancy 2.
// All operands single fp16: S = Q^T K (1 term), PV = P V (1 term).
// smem: Q[64][136], K[64][72], V[64][72] = 35 KB.
// ---------------------------------------------------------------------------
#define AQH2 136
#define AKH 72
#define SM_SCALE_LOG2 0.1803368801f

__global__ void __launch_bounds__(256, 2) attn_mma_kernel(
    const ushort_t* __restrict__ qkvp, ushort_t* __restrict__ outp) {
  extern __shared__ __align__(16) ushort_t smem[];
  ushort_t* Qs = smem;                  // 64*136
  ushort_t* Ks = Qs + 64 * AQH2;        // 64*72
  ushort_t* Vs = Ks + 64 * AKH;         // 64*72 (transposed [s][d])

  const int tid = threadIdx.x, lane = tid & 31, warp = tid >> 5;
  const int bh_ = blockIdx.y;
  const int b = bh_ >> 3, h = bh_ & 7;
  const int t0 = blockIdx.x * 128;

  const ushort_t* qp = qkvp + ((size_t)b * OC3 + h * HD) * NHW;
  const ushort_t* kp = qp + (size_t)NC * NHW;
  const ushort_t* vp = qp + (size_t)2 * NC * NHW;

  // Load Q [d 64][t 128]
#pragma unroll
  for (int i = 0; i < 4; i++) {
    const int idx = i * 256 + tid;
    const int r = idx >> 4, c = idx & 15;
    *(uint4*)(Qs + r * AQH2 + c * 8) =
        *(const uint4*)(qp + (size_t)r * NHW + t0 + c * 8);
  }
  __syncthreads();

  const int a_kr = ((lane >> 4) << 3) + (lane & 7);
  const int a_mc = ((lane >> 3) & 1) << 3;
  const int b_g = lane >> 3;
  const int b_row = ((b_g & 1) << 3) + (lane & 7);
  const int b_col = (b_g >> 1) << 3;

  // Hoist Q A-fragments (m16)
  uint32_t aq[4][4];
#pragma unroll
  for (int k4 = 0; k4 < 4; k4++) {
    const int ao = (k4 * 16 + a_kr) * AQH2 + warp * 16 + a_mc;
    ldsm_x4_t(aq[k4], smem_u32(&Qs[ao]));
  }

  float o8[8][4] = {};
  float m0 = -1e30f, m1 = -1e30f, l0 = 0.f, l1 = 0.f;

#pragma unroll 1
  for (int s0 = 0; s0 < NHW; s0 += 64) {
    // K tile [d 64][s 64]
#pragma unroll
    for (int i = 0; i < 2; i++) {
      const int idx = i * 256 + tid;
      const int r = idx >> 3, c = idx & 7;
      *(uint4*)(Ks + r * AKH + c * 8) =
          *(const uint4*)(kp + (size_t)r * NHW + s0 + c * 8);
    }
    // V tile transposed [s 64][d 64]
    {
      const int dp = tid & 31, sc = tid >> 5;
      uint4 r0 = *(const uint4*)(vp + (size_t)(2 * dp) * NHW + s0 + sc * 8);
      uint4 r1 = *(const uint4*)(vp + (size_t)(2 * dp + 1) * NHW + s0 + sc * 8);
      uint32_t q0[4] = {r0.x, r0.y, r0.z, r0.w};
      uint32_t q1[4] = {r1.x, r1.y, r1.z, r1.w};
#pragma unroll
      for (int j2 = 0; j2 < 4; j2++) {
        uint32_t a = q0[j2], bq = q1[j2];
        uint32_t w0 = (a & 0xffffu) | (bq << 16);
        uint32_t w1 = (a >> 16) | (bq & 0xffff0000u);
        const int s = sc * 8 + 2 * j2;
        *(uint32_t*)&Vs[s * AKH + 2 * dp] = w0;
        *(uint32_t*)&Vs[(s + 1) * AKH + 2 * dp] = w1;
      }
    }
    __syncthreads();

    // ---- S = Q^T K (m16 x n64, k=64), 1 term ----
    float sacc[8][4] = {};
#pragma unroll
    for (int k4 = 0; k4 < 4; k4++) {
#pragma unroll
      for (int nb = 0; nb < 4; nb++) {
        uint32_t kb[4];
        const int bo = (k4 * 16 + b_row) * AKH + nb * 16 + b_col;
        ldsm_x4_t(kb, smem_u32(&Ks[bo]));
        mma16816(sacc[2 * nb], aq[k4], &kb[0]);
        mma16816(sacc[2 * nb + 1], aq[k4], &kb[2]);
      }
    }

    // ---- online softmax (base-2) ----
    float mt0 = -1e30f, mt1 = -1e30f;
#pragma unroll
    for (int f = 0; f < 8; f++) {
      sacc[f][0] *= SM_SCALE_LOG2;
      sacc[f][1] *= SM_SCALE_LOG2;
      sacc[f][2] *= SM_SCALE_LOG2;
      sacc[f][3] *= SM_SCALE_LOG2;
      mt0 = fmaxf(mt0, fmaxf(sacc[f][0], sacc[f][1]));
      mt1 = fmaxf(mt1, fmaxf(sacc[f][2], sacc[f][3]));
    }
    mt0 = fmaxf(mt0, __shfl_xor_sync(0xffffffffu, mt0, 1));
    mt0 = fmaxf(mt0, __shfl_xor_sync(0xffffffffu, mt0, 2));
    mt1 = fmaxf(mt1, __shfl_xor_sync(0xffffffffu, mt1, 1));
    mt1 = fmaxf(mt1, __shfl_xor_sync(0xffffffffu, mt1, 2));
    const float mn0 = fmaxf(m0, mt0), mn1 = fmaxf(m1, mt1);
    const float fac0 = ex2f(m0 - mn0), fac1 = ex2f(m1 - mn1);
    m0 = mn0; m1 = mn1;
    float rs0 = 0.f, rs1 = 0.f;
#pragma unroll
    for (int f = 0; f < 8; f++) {
      sacc[f][0] = ex2f(sacc[f][0] - mn0);
      sacc[f][1] = ex2f(sacc[f][1] - mn0);
      sacc[f][2] = ex2f(sacc[f][2] - mn1);
      sacc[f][3] = ex2f(sacc[f][3] - mn1);
      rs0 += sacc[f][0] + sacc[f][1];
      rs1 += sacc[f][2] + sacc[f][3];
    }
    rs0 += __shfl_xor_sync(0xffffffffu, rs0, 1);
    rs0 += __shfl_xor_sync(0xffffffffu, rs0, 2);
    rs1 += __shfl_xor_sync(0xffffffffu, rs1, 1);
    rs1 += __shfl_xor_sync(0xffffffffu, rs1, 2);
    l0 = l0 * fac0 + rs0;
    l1 = l1 * fac1 + rs1;
#pragma unroll
    for (int f = 0; f < 8; f++) {
      o8[f][0] *= fac0; o8[f][1] *= fac0;
      o8[f][2] *= fac1; o8[f][3] *= fac1;
    }

    // ---- pack P (single fp16) ----
    uint32_t Ph[4][4];
#pragma unroll
    for (int f = 0; f < 8; f++) {
      const int k8 = f >> 1, sl = (f & 1) << 1;
      Ph[k8][sl] = packh2(sacc[f][0], sacc[f][1]);
      Ph[k8][sl + 1] = packh2(sacc[f][2], sacc[f][3]);
    }

    // ---- O += P V (m16 x n64, k=64), 1 term ----
#pragma unroll
    for (int k8 = 0; k8 < 4; k8++) {
#pragma unroll
      for (int nb = 0; nb < 4; nb++) {
        uint32_t vv[4];
        const int vo = (k8 * 16 + b_row) * AKH + nb * 16 + b_col;
        ldsm_x4_t(vv, smem_u32(&Vs[vo]));
        mma16816(o8[2 * nb], Ph[k8], &vv[0]);
        mma16816(o8[2 * nb + 1], Ph[k8], &vv[2]);
      }
    }
    __syncthreads();
  }

  // ---- epilogue: normalize, stage [d 64][t 128] f32 across ALL smem ----
  float* Ost = (float*)smem;  // 64*132*4 = 33792 B <= 35840 B total smem
  const float inv0 = 1.f / l0, inv1 = 1.f / l1;
  const int tl = warp * 16 + (lane >> 2);
#pragma unroll
  for (int f = 0; f < 8; f++) {
    const int d = f * 8 + ((lane & 3) << 1);
    Ost[d * 132 + tl] = o8[f][0] * inv0;
    Ost[(d + 1) * 132 + tl] = o8[f][1] * inv0;
    Ost[d * 132 + tl + 8] = o8[f][2] * inv1;
    Ost[(d + 1) * 132 + tl + 8] = o8[f][3] * inv1;
  }
  __syncthreads();
#pragma unroll
  for (int i = 0; i < 4; i++) {
    const int idx = i * 256 + tid;
    const int r = idx >> 4, c = idx & 15;
    const float* src = &Ost[r * 132 + c * 8];
    uint32_t hu[4];
#pragma unroll
    for (int j = 0; j < 4; j++) hu[j] = packh2(src[2 * j], src[2 * j + 1]);
    const size_t off = ((size_t)b * NC + h * HD + r) * NHW + t0 + c * 8;
    *(uint4*)(outp + off) = make_uint4(hu[0], hu[1], hu[2], hu[3]);
  }
}

// ---------------------------------------------------------------------------
extern "C" void kernel_launch(void* const* d_in, const int* in_sizes, int n_in,
                              void* d_out, int out_size) {
  const float* x = (const float*)d_in[0];
  const float* gn_gamma = (const float*)d_in[1];
  const float* gn_beta = (const float*)d_in[2];
  const float* qkv_w = (const float*)d_in[3];
  const float* qkv_b = (const float*)d_in[4];
  const float* proj_w = (const float*)d_in[5];
  const float* proj_b = (const float*)d_in[6];
  float* out = (float*)d_out;

  ushort_t *wq, *wp, *xn, *qkvp, *att;
  cudaGetSymbolAddress((void**)&wq, g_wq);
  cudaGetSymbolAddress((void**)&wp, g_wp);
  cudaGetSymbolAddress((void**)&xn, g_xn);
  cudaGetSymbolAddress((void**)&qkvp, g_qkv);
  cudaGetSymbolAddress((void**)&att, g_att);

  const int ATT_SMEM =
      (64 * AQH2 + 2 * 64 * AKH) * (int)sizeof(ushort_t);  // 35840 B
  cudaFuncSetAttribute(attn_mma_kernel,
                       cudaFuncAttributeMaxDynamicSharedMemorySize, ATT_SMEM);
  cudaFuncSetAttribute(gemm_fp16_kernel<OC3, true>,
                       cudaFuncAttributeMaxDynamicSharedMemorySize, GEMM_SMEM);
  cudaFuncSetAttribute(gemm_fp16_kernel<NC, false>,
                       cudaFuncAttributeMaxDynamicSharedMemorySize, GEMM_SMEM);

  gn_kernel<<<NB * NG, 256>>>(x, gn_gamma, gn_beta);
  prep_w_kernel<<<(OC3 * NC + NC * NC) / 4 / 256, 256>>>(qkv_w, proj_w);
  gemm_fp16_kernel<OC3, true><<<dim3(8, 12, NB), 256, GEMM_SMEM>>>(
      wq, qkv_b, xn, nullptr, nullptr, qkvp);
  attn_mma_kernel<<<dim3(8, NB * NHEADS), 256, ATT_SMEM>>>(qkvp, att);
  gemm_fp16_kernel<NC, false><<<dim3(8, 4, NB), 256, GEMM_SMEM>>>(
      wp, proj_b, att, x, out, nullptr);
}

// round 17
// speedup vs baseline: 4.2744x; 1.1664x over previous
#include <cuda_runtime.h>
#include <cuda_fp16.h>
#include <math.h>
#include <stdint.h>

#define NB 16
#define NC 512
#define NHW 1024
#define NHEADS 8
#define HD 64
#define NG 32
#define OC3 1536
#define GN_EPS 1e-5f

typedef unsigned short ushort_t;

// Scratch (static device globals — allocation-free per harness rules)
__device__ ushort_t g_wq[(size_t)OC3 * NC];       // single fp16
__device__ ushort_t g_wp[(size_t)NC * NC];        // single fp16
__device__ ushort_t g_xn[(size_t)NB * NC * NHW];  // single fp16
__device__ ushort_t g_qkv[(size_t)NB * OC3 * NHW];
__device__ ushort_t g_att[(size_t)NB * NC * NHW];

// ============================ helpers ======================================
__device__ __forceinline__ uint32_t smem_u32(const void* p) {
  uint32_t a;
  asm("{ .reg .u64 t; cvta.to.shared.u64 t, %1; cvt.u32.u64 %0, t; }"
      : "=r"(a) : "l"(p));
  return a;
}
__device__ __forceinline__ float ex2f(float x) {
  float r;
  asm("ex2.approx.ftz.f32 %0, %1;" : "=f"(r) : "f"(x));
  return r;
}
__device__ __forceinline__ uint32_t packh2(float v0, float v1) {
  __half2 h = __floats2half2_rn(v0, v1);
  return *(uint32_t*)&h;
}
__device__ __forceinline__ void ldsm_x4(uint32_t* r, uint32_t addr) {
  asm volatile("ldmatrix.sync.aligned.m8n8.x4.shared.b16 {%0,%1,%2,%3}, [%4];"
               : "=r"(r[0]), "=r"(r[1]), "=r"(r[2]), "=r"(r[3]) : "r"(addr));
}
__device__ __forceinline__ void ldsm_x4_t(uint32_t* r, uint32_t addr) {
  asm volatile(
      "ldmatrix.sync.aligned.m8n8.x4.trans.shared.b16 {%0,%1,%2,%3}, [%4];"
      : "=r"(r[0]), "=r"(r[1]), "=r"(r[2]), "=r"(r[3]) : "r"(addr));
}
__device__ __forceinline__ void mma16816(float* d, const uint32_t* a,
                                         const uint32_t* b) {
  asm volatile(
      "mma.sync.aligned.m16n8k16.row.col.f32.f16.f16.f32 "
      "{%0,%1,%2,%3}, {%4,%5,%6,%7}, {%8,%9}, {%0,%1,%2,%3};"
      : "+f"(d[0]), "+f"(d[1]), "+f"(d[2]), "+f"(d[3])
      : "r"(a[0]), "r"(a[1]), "r"(a[2]), "r"(a[3]), "r"(b[0]), "r"(b[1]));
}
__device__ __forceinline__ void cp_async16(uint32_t dst, const void* src) {
  asm volatile("cp.async.cg.shared.global [%0], [%1], 16;" :: "r"(dst),
               "l"(src));
}
#define CP_COMMIT() asm volatile("cp.async.commit_group;" ::: "memory")
#define CP_WAIT(n) asm volatile("cp.async.wait_group %0;" :: "n"(n) : "memory")

#define SM_SCALE_LOG2 0.1803368801f  // 0.125 * log2(e)

// ---------------------------------------------------------------------------
// Weight prep: fp32 -> single fp16
// ---------------------------------------------------------------------------
__global__ void __launch_bounds__(256) prep_w_kernel(
    const float* __restrict__ qkv_w, const float* __restrict__ proj_w) {
  const int idx = blockIdx.x * 256 + threadIdx.x;
  const int nq = OC3 * NC / 4;
  const float* src;
  ushort_t* dh;
  int off;
  if (idx < nq) {
    src = qkv_w; dh = g_wq; off = idx * 4;
  } else {
    src = proj_w; dh = g_wp; off = (idx - nq) * 4;
  }
  float4 v = *(const float4*)(src + off);
  *(uint2*)(dh + off) = make_uint2(packh2(v.x, v.y), packh2(v.z, v.w));
}

// ---------------------------------------------------------------------------
// GroupNorm -> single fp16 plane
// ---------------------------------------------------------------------------
__global__ void __launch_bounds__(256) gn_kernel(
    const float* __restrict__ x, const float* __restrict__ gamma,
    const float* __restrict__ beta) {
  const int bg = blockIdx.x;
  const int g = bg & (NG - 1);
  const size_t base = (size_t)bg * (NC / NG) * NHW;
  const float* px = x + base;
  ushort_t* po = g_xn + base;
  const int tid = threadIdx.x;

  float s = 0.f, q = 0.f;
#pragma unroll
  for (int k = 0; k < 16; k++) {
    float4 v = *(const float4*)(px + (size_t)(tid + k * 256) * 4);
    s += v.x + v.y + v.z + v.w;
    q += v.x * v.x + v.y * v.y + v.z * v.z + v.w * v.w;
  }
#pragma unroll
  for (int off = 16; off; off >>= 1) {
    s += __shfl_xor_sync(0xffffffffu, s, off);
    q += __shfl_xor_sync(0xffffffffu, q, off);
  }
  __shared__ float ss[8], sq[8];
  __shared__ float s_mean, s_inv;
  const int w = tid >> 5;
  if ((tid & 31) == 0) { ss[w] = s; sq[w] = q; }
  __syncthreads();
  if (tid == 0) {
    float ts = 0.f, tq = 0.f;
#pragma unroll
    for (int i = 0; i < 8; i++) { ts += ss[i]; tq += sq[i]; }
    float mean = ts * (1.f / 16384.f);
    float var = tq * (1.f / 16384.f) - mean * mean;
    s_mean = mean;
    s_inv = rsqrtf(var + GN_EPS);
  }
  __syncthreads();
  const float mean = s_mean, inv = s_inv;
#pragma unroll
  for (int k = 0; k < 16; k++) {
    size_t off = (size_t)(tid + k * 256) * 4;
    int c = g * 16 + (int)(off >> 10);
    float ga = gamma[c], be = beta[c];
    float4 v = *(const float4*)(px + off);
    v.x = (v.x - mean) * inv * ga + be;
    v.y = (v.y - mean) * inv * ga + be;
    v.z = (v.z - mean) * inv * ga + be;
    v.w = (v.w - mean) * inv * ga + be;
    *(uint2*)(po + off) = make_uint2(packh2(v.x, v.y), packh2(v.z, v.w));
  }
}

// ---------------------------------------------------------------------------
// fp16 GEMM, single-term, cp.async double-buffered.
// Tile 128(o) x 128(t), K-chunk 32; 8 warps = 4m x 2n; warp 32x64.
// EMIT: rows o<NC (=Q) are pre-scaled by 0.125*log2(e) for attention.
// ---------------------------------------------------------------------------
#define SAH 40
#define SBH 136
#define A_ELE (128 * SAH)
#define B_ELE (32 * SBH)
#define BUF_ELE (A_ELE + B_ELE)
#define GEMM_SMEM (2 * BUF_ELE * (int)sizeof(ushort_t))
#define NCH (NC / 32)

template <int OC, bool EMIT>
__global__ void __launch_bounds__(256, 2) gemm_fp16_kernel(
    const ushort_t* __restrict__ A, const float* __restrict__ bias,
    const ushort_t* __restrict__ B, const float* __restrict__ R,
    float* __restrict__ Yf, ushort_t* __restrict__ Yh) {
  extern __shared__ __align__(16) ushort_t smem[];

  const int tid = threadIdx.x, lane = tid & 31, wid = tid >> 5;
  const int wm = wid >> 1, wn = wid & 1;
  const int bz = blockIdx.z;
  const int o0 = blockIdx.y * 128;
  const int t0 = blockIdx.x * 128;
  const size_t bb = (size_t)bz * NC * NHW;

  const int a_r = lane & 15, a_c = (lane >> 4) << 3;
  const int b_g = lane >> 3;
  const int b_row = ((b_g & 1) << 3) + (lane & 7);
  const int b_col = (b_g >> 1) << 3;

  float acc[2][8][4] = {};

#define CP_CHUNK(kc, buf)                                                    \
  {                                                                          \
    ushort_t* Asm = smem + (buf)*BUF_ELE;                                    \
    ushort_t* Bsm = Asm + A_ELE;                                             \
    _Pragma("unroll") for (int i = 0; i < 2; i++) {                          \
      const int idx = i * 256 + tid;                                         \
      const int r = idx >> 2, cc = idx & 3;                                  \
      cp_async16(smem_u32(&Asm[r * SAH + cc * 8]),                           \
                 A + (size_t)(o0 + r) * NC + (kc) + cc * 8);                 \
    }                                                                        \
    _Pragma("unroll") for (int i = 0; i < 2; i++) {                          \
      const int idx = i * 256 + tid;                                         \
      const int r = idx >> 4, cc = idx & 15;                                 \
      cp_async16(smem_u32(&Bsm[r * SBH + cc * 8]),                           \
                 B + bb + (size_t)((kc) + r) * NHW + t0 + cc * 8);           \
    }                                                                        \
  }

  CP_CHUNK(0, 0);
  CP_COMMIT();

#pragma unroll 1
  for (int chunk = 0; chunk < NCH; chunk++) {
    const int cur = chunk & 1;
    __syncthreads();
    if (chunk < NCH - 1) {
      CP_CHUNK((chunk + 1) * 32, cur ^ 1);
      CP_COMMIT();
      CP_WAIT(1);
    } else {
      CP_WAIT(0);
    }
    __syncthreads();

    const ushort_t* Asm = smem + cur * BUF_ELE;
    const ushort_t* Bsm = Asm + A_ELE;
#pragma unroll
    for (int ks = 0; ks < 2; ks++) {
      const int kb = ks * 16;
      uint32_t ah[2][4];
#pragma unroll
      for (int mf = 0; mf < 2; mf++) {
        const int ao = (wm * 32 + mf * 16 + a_r) * SAH + kb + a_c;
        ldsm_x4(ah[mf], smem_u32(&Asm[ao]));
      }
#pragma unroll
      for (int nb = 0; nb < 4; nb++) {
        uint32_t bh[4];
        const int bo = (kb + b_row) * SBH + wn * 64 + nb * 16 + b_col;
        ldsm_x4_t(bh, smem_u32(&Bsm[bo]));
#pragma unroll
        for (int mf = 0; mf < 2; mf++) {
          mma16816(acc[mf][2 * nb], ah[mf], &bh[0]);
          mma16816(acc[mf][2 * nb + 1], ah[mf], &bh[2]);
        }
      }
    }
  }
#undef CP_CHUNK

#pragma unroll
  for (int mf = 0; mf < 2; mf++)
#pragma unroll
    for (int nf = 0; nf < 8; nf++) {
      const int o = o0 + wm * 32 + mf * 16 + (lane >> 2);
      const int t = t0 + wn * 64 + nf * 8 + ((lane & 3) << 1);
      const size_t off0 = ((size_t)bz * OC + o) * NHW + t;
      const size_t off1 = off0 + (size_t)8 * NHW;
      const float bi0 = bias[o], bi1 = bias[o + 8];
      float y0 = acc[mf][nf][0] + bi0, y1 = acc[mf][nf][1] + bi0;
      float y2 = acc[mf][nf][2] + bi1, y3 = acc[mf][nf][3] + bi1;
      if (EMIT) {
        // Pre-scale Q rows (o < NC) by 0.125*log2(e) for base-2 softmax.
        const float qs0 = (o < NC) ? SM_SCALE_LOG2 : 1.f;
        const float qs1 = (o + 8 < NC) ? SM_SCALE_LOG2 : 1.f;
        *(uint32_t*)(Yh + off0) = packh2(y0 * qs0, y1 * qs0);
        *(uint32_t*)(Yh + off1) = packh2(y2 * qs1, y3 * qs1);
      } else {
        float2 r0 = *(const float2*)(R + off0);
        float2 r1 = *(const float2*)(R + off1);
        *(float2*)(Yf + off0) = make_float2(y0 + r0.x, y1 + r0.y);
        *(float2*)(Yf + off1) = make_float2(y2 + r1.x, y3 + r1.y);
      }
    }
}

// ---------------------------------------------------------------------------
// Flash attention: m16 warp tiles, 64-wide key tiles, occupancy 2.
// K and V both stored [d][s] (straight copies, cp.async double-buffered).
// S: trans-ldmatrix on K.  PV: NON-trans ldmatrix on V[d][s] (B col-major).
// Q arrives pre-scaled by 0.125*log2(e).
// smem: Q[64][136] + 2 x (K[64][72] + V[64][72]) = 53 KB.
// ---------------------------------------------------------------------------
#define AQH2 136
#define AKH 72
#define KV_ELE (64 * AKH)

__global__ void __launch_bounds__(256, 2) attn_mma_kernel(
    const ushort_t* __restrict__ qkvp, ushort_t* __restrict__ outp) {
  extern __shared__ __align__(16) ushort_t smem[];
  ushort_t* Qs = smem;                       // 64*136
  ushort_t* KV = Qs + 64 * AQH2;             // 2 stages x (K + V)

  const int tid = threadIdx.x, lane = tid & 31, warp = tid >> 5;
  const int bh_ = blockIdx.y;
  const int b = bh_ >> 3, h = bh_ & 7;
  const int t0 = blockIdx.x * 128;

  const ushort_t* qp = qkvp + ((size_t)b * OC3 + h * HD) * NHW;
  const ushort_t* kp = qp + (size_t)NC * NHW;
  const ushort_t* vp = qp + (size_t)2 * NC * NHW;

  // Load Q [d 64][t 128]
#pragma unroll
  for (int i = 0; i < 4; i++) {
    const int idx = i * 256 + tid;
    const int r = idx >> 4, c = idx & 15;
    *(uint4*)(Qs + r * AQH2 + c * 8) =
        *(const uint4*)(qp + (size_t)r * NHW + t0 + c * 8);
  }

  const int a_kr = ((lane >> 4) << 3) + (lane & 7);
  const int a_mc = ((lane >> 3) & 1) << 3;
  const int b_g = lane >> 3;
  const int b_row = ((b_g & 1) << 3) + (lane & 7);
  const int b_col = (b_g >> 1) << 3;

  // K/V tile prefetch (both [d 64][s 64], straight copies)
#define CP_KV(s0, buf)                                                       \
  {                                                                          \
    ushort_t* Ksm = KV + (buf) * (2 * KV_ELE);                               \
    ushort_t* Vsm = Ksm + KV_ELE;                                            \
    _Pragma("unroll") for (int i = 0; i < 2; i++) {                          \
      const int idx = i * 256 + tid;                                         \
      const int r = idx >> 3, c = idx & 7;                                   \
      cp_async16(smem_u32(&Ksm[r * AKH + c * 8]),                            \
                 kp + (size_t)r * NHW + (s0) + c * 8);                       \
      cp_async16(smem_u32(&Vsm[r * AKH + c * 8]),                            \
                 vp + (size_t)r * NHW + (s0) + c * 8);                       \
    }                                                                        \
  }

  CP_KV(0, 0);
  CP_COMMIT();
  __syncthreads();

  // Hoist Q A-fragments (m16)
  uint32_t aq[4][4];
#pragma unroll
  for (int k4 = 0; k4 < 4; k4++) {
    const int ao = (k4 * 16 + a_kr) * AQH2 + warp * 16 + a_mc;
    ldsm_x4_t(aq[k4], smem_u32(&Qs[ao]));
  }

  float o8[8][4] = {};
  float m0 = -1e30f, m1 = -1e30f, l0 = 0.f, l1 = 0.f;

#pragma unroll 1
  for (int tile = 0; tile < NHW / 64; tile++) {
    const int cur = tile & 1;
    __syncthreads();  // all warps done reading buf cur^1
    if (tile < NHW / 64 - 1) {
      CP_KV((tile + 1) * 64, cur ^ 1);
      CP_COMMIT();
      CP_WAIT(1);
    } else {
      CP_WAIT(0);
    }
    __syncthreads();

    const ushort_t* Ks = KV + cur * (2 * KV_ELE);
    const ushort_t* Vs = Ks + KV_ELE;

    // ---- S = Q^T K (m16 x n64, k=64) ----
    float sacc[8][4] = {};
#pragma unroll
    for (int k4 = 0; k4 < 4; k4++) {
#pragma unroll
      for (int nb = 0; nb < 4; nb++) {
        uint32_t kb[4];
        const int bo = (k4 * 16 + b_row) * AKH + nb * 16 + b_col;
        ldsm_x4_t(kb, smem_u32(&Ks[bo]));
        mma16816(sacc[2 * nb], aq[k4], &kb[0]);
        mma16816(sacc[2 * nb + 1], aq[k4], &kb[2]);
      }
    }

    // ---- online softmax (base-2; Q pre-scaled) ----
    float mt0 = -1e30f, mt1 = -1e30f;
#pragma unroll
    for (int f = 0; f < 8; f++) {
      mt0 = fmaxf(mt0, fmaxf(sacc[f][0], sacc[f][1]));
      mt1 = fmaxf(mt1, fmaxf(sacc[f][2], sacc[f][3]));
    }
    mt0 = fmaxf(mt0, __shfl_xor_sync(0xffffffffu, mt0, 1));
    mt0 = fmaxf(mt0, __shfl_xor_sync(0xffffffffu, mt0, 2));
    mt1 = fmaxf(mt1, __shfl_xor_sync(0xffffffffu, mt1, 1));
    mt1 = fmaxf(mt1, __shfl_xor_sync(0xffffffffu, mt1, 2));
    const float mn0 = fmaxf(m0, mt0), mn1 = fmaxf(m1, mt1);
    const float fac0 = ex2f(m0 - mn0), fac1 = ex2f(m1 - mn1);
    m0 = mn0; m1 = mn1;
    float rs0 = 0.f, rs1 = 0.f;
#pragma unroll
    for (int f = 0; f < 8; f++) {
      sacc[f][0] = ex2f(sacc[f][0] - mn0);
      sacc[f][1] = ex2f(sacc[f][1] - mn0);
      sacc[f][2] = ex2f(sacc[f][2] - mn1);
      sacc[f][3] = ex2f(sacc[f][3] - mn1);
      rs0 += sacc[f][0] + sacc[f][1];
      rs1 += sacc[f][2] + sacc[f][3];
    }
    rs0 += __shfl_xor_sync(0xffffffffu, rs0, 1);
    rs0 += __shfl_xor_sync(0xffffffffu, rs0, 2);
    rs1 += __shfl_xor_sync(0xffffffffu, rs1, 1);
    rs1 += __shfl_xor_sync(0xffffffffu, rs1, 2);
    l0 = l0 * fac0 + rs0;
    l1 = l1 * fac1 + rs1;
#pragma unroll
    for (int f = 0; f < 8; f++) {
      o8[f][0] *= fac0; o8[f][1] *= fac0;
      o8[f][2] *= fac1; o8[f][3] *= fac1;
    }

    // ---- pack P (single fp16) ----
    uint32_t Ph[4][4];
#pragma unroll
    for (int f = 0; f < 8; f++) {
      const int k8 = f >> 1, sl = (f & 1) << 1;
      Ph[k8][sl] = packh2(sacc[f][0], sacc[f][1]);
      Ph[k8][sl + 1] = packh2(sacc[f][2], sacc[f][3]);
    }

    // ---- O += P V: non-trans ldmatrix on V[d][s] (B col-major) ----
#pragma unroll
    for (int k8 = 0; k8 < 4; k8++) {
#pragma unroll
      for (int nb = 0; nb < 4; nb++) {
        uint32_t vv[4];
        const int vo = (nb * 16 + a_kr) * AKH + k8 * 16 + a_mc;
        ldsm_x4(vv, smem_u32(&Vs[vo]));
        mma16816(o8[2 * nb], Ph[k8], &vv[0]);
        mma16816(o8[2 * nb + 1], Ph[k8], &vv[2]);
      }
    }
  }
#undef CP_KV

  // ---- epilogue: normalize, stage [d 64][t 128] f32 across smem ----
  __syncthreads();
  float* Ost = (float*)smem;  // 64*132*4 = 33792 B <= 53 KB smem
  const float inv0 = 1.f / l0, inv1 = 1.f / l1;
  const int tl = warp * 16 + (lane >> 2);
#pragma unroll
  for (int f = 0; f < 8; f++) {
    const int d = f * 8 + ((lane & 3) << 1);
    Ost[d * 132 + tl] = o8[f][0] * inv0;
    Ost[(d + 1) * 132 + tl] = o8[f][1] * inv0;
    Ost[d * 132 + tl + 8] = o8[f][2] * inv1;
    Ost[(d + 1) * 132 + tl + 8] = o8[f][3] * inv1;
  }
  __syncthreads();
#pragma unroll
  for (int i = 0; i < 4; i++) {
    const int idx = i * 256 + tid;
    const int r = idx >> 4, c = idx & 15;
    const float* src = &Ost[r * 132 + c * 8];
    uint32_t hu[4];
#pragma unroll
    for (int j = 0; j < 4; j++) hu[j] = packh2(src[2 * j], src[2 * j + 1]);
    const size_t off = ((size_t)b * NC + h * HD + r) * NHW + t0 + c * 8;
    *(uint4*)(outp + off) = make_uint4(hu[0], hu[1], hu[2], hu[3]);
  }
}

// ---------------------------------------------------------------------------
extern "C" void kernel_launch(void* const* d_in, const int* in_sizes, int n_in,
                              void* d_out, int out_size) {
  const float* x = (const float*)d_in[0];
  const float* gn_gamma = (const float*)d_in[1];
  const float* gn_beta = (const float*)d_in[2];
  const float* qkv_w = (const float*)d_in[3];
  const float* qkv_b = (const float*)d_in[4];
  const float* proj_w = (const float*)d_in[5];
  const float* proj_b = (const float*)d_in[6];
  float* out = (float*)d_out;

  ushort_t *wq, *wp, *xn, *qkvp, *att;
  cudaGetSymbolAddress((void**)&wq, g_wq);
  cudaGetSymbolAddress((void**)&wp, g_wp);
  cudaGetSymbolAddress((void**)&xn, g_xn);
  cudaGetSymbolAddress((void**)&qkvp, g_qkv);
  cudaGetSymbolAddress((void**)&att, g_att);

  const int ATT_SMEM =
      (64 * AQH2 + 4 * 64 * AKH) * (int)sizeof(ushort_t);  // 54272 B
  cudaFuncSetAttribute(attn_mma_kernel,
                       cudaFuncAttributeMaxDynamicSharedMemorySize, ATT_SMEM);
  cudaFuncSetAttribute(gemm_fp16_kernel<OC3, true>,
                       cudaFuncAttributeMaxDynamicSharedMemorySize, GEMM_SMEM);
  cudaFuncSetAttribute(gemm_fp16_kernel<NC, false>,
                       cudaFuncAttributeMaxDynamicSharedMemorySize, GEMM_SMEM);

  gn_kernel<<<NB * NG, 256>>>(x, gn_gamma, gn_beta);
  prep_w_kernel<<<(OC3 * NC + NC * NC) / 4 / 256, 256>>>(qkv_w, proj_w);
  gemm_fp16_kernel<OC3, true><<<dim3(8, 12, NB), 256, GEMM_SMEM>>>(
      wq, qkv_b, xn, nullptr, nullptr, qkvp);
  attn_mma_kernel<<<dim3(8, NB * NHEADS), 256, ATT_SMEM>>>(qkvp, att);
  gemm_fp16_kernel<NC, false><<<dim3(8, 4, NB), 256, GEMM_SMEM>>>(
      wp, proj_b, att, x, out, nullptr);
}